// round 1
// baseline (speedup 1.0000x reference)
#include <cuda_runtime.h>

// Problem constants (fixed by setup_inputs)
constexpr int B_  = 2;
constexpr int L_  = 256;
constexpr int D_  = 4096;
constexpr int H_  = 32;
constexpr int Dh_ = 128;
constexpr int S_  = 4224;          // SINK + LOCAL
constexpr int SINK_ = 128;
constexpr int WINS_ = S_ - L_;     // 3968: queries i see j <= WINS_ + i
constexpr int M_  = B_ * L_;       // 512 rows

// Scratch (device globals: allocation-free)
__device__ float g_q[M_ * D_];
__device__ float g_k[M_ * D_];
__device__ float g_v[M_ * D_];
__device__ float g_o[M_ * D_];

// ---------------------------------------------------------------------------
// SGEMM: C[M,N] = A[M,K] @ W[K,N], row-major. M%64==0, N%64==0, K%16==0.
// BM=BN=64, BK=16, 256 threads, 4x4 per thread.
// ---------------------------------------------------------------------------
__global__ __launch_bounds__(256) void sgemm64(const float* __restrict__ A,
                                               const float* __restrict__ W,
                                               float* __restrict__ C,
                                               int N, int K) {
    __shared__ float As[16][68];   // [k][m], padded (conflict mitigation)
    __shared__ float Bs[16][64];   // [k][n]

    const int tid = threadIdx.x;
    const int tr = tid >> 4;            // 0..15  (m group)
    const int tc = tid & 15;            // 0..15  (n group)
    const int ar = tid >> 2;            // 0..63  A row in tile
    const int ac = (tid & 3) << 2;      // 0,4,8,12
    const int br = tid >> 4;            // 0..15  W row in tile
    const int bc = (tid & 15) << 2;     // 0..60

    const int m0 = blockIdx.y * 64;
    const int n0 = blockIdx.x * 64;

    const float* Ap = A + (long)(m0 + ar) * K + ac;
    const float* Wp = W + (long)br * N + n0 + bc;

    float c[4][4] = {};

    for (int k0 = 0; k0 < K; k0 += 16) {
        float4 av = *(const float4*)(Ap + k0);
        float4 bv = *(const float4*)(Wp + (long)k0 * N);
        As[ac + 0][ar] = av.x;
        As[ac + 1][ar] = av.y;
        As[ac + 2][ar] = av.z;
        As[ac + 3][ar] = av.w;
        *(float4*)&Bs[br][bc] = bv;
        __syncthreads();

#pragma unroll
        for (int k = 0; k < 16; ++k) {
            float4 a = *(const float4*)&As[k][tr << 2];
            float4 b = *(const float4*)&Bs[k][tc << 2];
            c[0][0] += a.x * b.x; c[0][1] += a.x * b.y; c[0][2] += a.x * b.z; c[0][3] += a.x * b.w;
            c[1][0] += a.y * b.x; c[1][1] += a.y * b.y; c[1][2] += a.y * b.z; c[1][3] += a.y * b.w;
            c[2][0] += a.z * b.x; c[2][1] += a.z * b.y; c[2][2] += a.z * b.z; c[2][3] += a.z * b.w;
            c[3][0] += a.w * b.x; c[3][1] += a.w * b.y; c[3][2] += a.w * b.z; c[3][3] += a.w * b.w;
        }
        __syncthreads();
    }

#pragma unroll
    for (int i = 0; i < 4; ++i) {
        float4 r = make_float4(c[i][0], c[i][1], c[i][2], c[i][3]);
        *(float4*)(C + (long)(m0 + (tr << 2) + i) * N + n0 + (tc << 2)) = r;
    }
}

// ---------------------------------------------------------------------------
// Per-head RMSNorm over Dh=128, one warp per row. X: [M*H, 128] in place.
// ---------------------------------------------------------------------------
__global__ __launch_bounds__(256) void rmsnorm_k(float* __restrict__ X,
                                                 const float* __restrict__ w) {
    const int row  = (blockIdx.x * 256 + threadIdx.x) >> 5;
    const int lane = threadIdx.x & 31;
    float* p = X + (long)row * 128 + lane * 4;
    float4 v = *(float4*)p;
    float ss = v.x * v.x + v.y * v.y + v.z * v.z + v.w * v.w;
#pragma unroll
    for (int o = 16; o; o >>= 1) ss += __shfl_xor_sync(0xffffffffu, ss, o);
    float r = rsqrtf(ss * (1.0f / 128.0f) + 1e-6f);
    float4 wv = *(const float4*)(w + lane * 4);
    v.x *= r * wv.x; v.y *= r * wv.y; v.z *= r * wv.z; v.w *= r * wv.w;
    *(float4*)p = v;
}

// ---------------------------------------------------------------------------
// Flash attention. Block: 256 threads, 32 queries. Grid: (L/32, H, B).
// Cache layout remap (no copy): pos s -> cache[s] (s<128), cache[s+L]
// (128<=s<3968), new K/V row s-3968 otherwise.
// Thread map: r = tid>>3 (query row 0..31), 8 lanes per row split Dh into 16s.
// ---------------------------------------------------------------------------
__global__ __launch_bounds__(256) void attn_kernel(const float* __restrict__ Q,
                                                   const float* __restrict__ Kn,
                                                   const float* __restrict__ Vn,
                                                   const float* __restrict__ cK,
                                                   const float* __restrict__ cV,
                                                   float* __restrict__ O) {
    __shared__ float Ks[32][128];
    __shared__ float Vs[32][128];

    const int tid = threadIdx.x;
    const int r   = tid >> 3;          // query row in tile
    const int d0  = (tid & 7) << 4;    // Dh slice start (16 dims)
    const int h   = blockIdx.y;
    const int b   = blockIdx.z;
    const int qi  = blockIdx.x * 32 + r;
    const int lim_g = WINS_ + qi;      // max allowed key position

    const float scale = 0.08838834764831845f;  // 1/sqrt(128)

    // Load + pre-scale q slice
    float qreg[16];
    {
        const float* qp = Q + ((long)(b * L_ + qi) * H_ + h) * Dh_ + d0;
#pragma unroll
        for (int i = 0; i < 16; ++i) qreg[i] = qp[i] * scale;
    }

    float o[16];
#pragma unroll
    for (int i = 0; i < 16; ++i) o[i] = 0.0f;
    float m = -1e30f, l = 0.0f;

    // K/V tile load mapping (same thread map as compute)
    const int jrow = tid >> 3;
    const int jc   = (tid & 7) << 4;

    for (int t0 = 0; t0 < S_; t0 += 32) {
        // ---- load K/V tile ----
        {
            const int sg = t0 + jrow;
            const float *ksrc, *vsrc;
            if (sg < WINS_) {
                const int src = (sg < SINK_) ? sg : sg + L_;
                const long off = (((long)b * S_ + src) * H_ + h) * Dh_ + jc;
                ksrc = cK + off; vsrc = cV + off;
            } else {
                const long off = (((long)b * L_ + (sg - WINS_)) * H_ + h) * Dh_ + jc;
                ksrc = Kn + off; vsrc = Vn + off;
            }
            float4* kd = (float4*)&Ks[jrow][jc];
            float4* vd = (float4*)&Vs[jrow][jc];
            const float4* ksp = (const float4*)ksrc;
            const float4* vsp = (const float4*)vsrc;
#pragma unroll
            for (int i = 0; i < 4; ++i) { kd[i] = ksp[i]; vd[i] = vsp[i]; }
        }
        __syncthreads();

        // ---- logits (partial dot + 8-lane butterfly reduce) ----
        float p[32];
#pragma unroll
        for (int j = 0; j < 32; ++j) {
            const float4* kp = (const float4*)&Ks[j][d0];
            float4 k0v = kp[0], k1v = kp[1], k2v = kp[2], k3v = kp[3];
            float acc;
            acc  = qreg[0]  * k0v.x; acc += qreg[1]  * k0v.y;
            acc += qreg[2]  * k0v.z; acc += qreg[3]  * k0v.w;
            acc += qreg[4]  * k1v.x; acc += qreg[5]  * k1v.y;
            acc += qreg[6]  * k1v.z; acc += qreg[7]  * k1v.w;
            acc += qreg[8]  * k2v.x; acc += qreg[9]  * k2v.y;
            acc += qreg[10] * k2v.z; acc += qreg[11] * k2v.w;
            acc += qreg[12] * k3v.x; acc += qreg[13] * k3v.y;
            acc += qreg[14] * k3v.z; acc += qreg[15] * k3v.w;
            acc += __shfl_xor_sync(0xffffffffu, acc, 1);
            acc += __shfl_xor_sync(0xffffffffu, acc, 2);
            acc += __shfl_xor_sync(0xffffffffu, acc, 4);
            p[j] = (t0 + j <= lim_g) ? acc : -1e30f;
        }

        // ---- online softmax ----
        float mt = m;
#pragma unroll
        for (int j = 0; j < 32; ++j) mt = fmaxf(mt, p[j]);
        const float alpha = __expf(m - mt);
        m = mt;
        float ls = 0.0f;
#pragma unroll
        for (int j = 0; j < 32; ++j) { p[j] = __expf(p[j] - mt); ls += p[j]; }
        l = l * alpha + ls;
#pragma unroll
        for (int i = 0; i < 16; ++i) o[i] *= alpha;

        // ---- P @ V ----
#pragma unroll
        for (int j = 0; j < 32; ++j) {
            const float pj = p[j];
            const float4* vp = (const float4*)&Vs[j][d0];
            float4 v0 = vp[0], v1 = vp[1], v2 = vp[2], v3 = vp[3];
            o[0]  += pj * v0.x; o[1]  += pj * v0.y; o[2]  += pj * v0.z; o[3]  += pj * v0.w;
            o[4]  += pj * v1.x; o[5]  += pj * v1.y; o[6]  += pj * v1.z; o[7]  += pj * v1.w;
            o[8]  += pj * v2.x; o[9]  += pj * v2.y; o[10] += pj * v2.z; o[11] += pj * v2.w;
            o[12] += pj * v3.x; o[13] += pj * v3.y; o[14] += pj * v3.z; o[15] += pj * v3.w;
        }
        __syncthreads();
    }

    const float inv = 1.0f / l;
    float* op = O + ((long)(b * L_ + qi) * H_ + h) * Dh_ + d0;
#pragma unroll
    for (int i = 0; i < 16; ++i) op[i] = o[i] * inv;
}

// ---------------------------------------------------------------------------
extern "C" void kernel_launch(void* const* d_in, const int* in_sizes, int n_in,
                              void* d_out, int out_size) {
    const float* x  = (const float*)d_in[0];
    const float* ck = (const float*)d_in[1];
    const float* cv = (const float*)d_in[2];
    const float* Wq = (const float*)d_in[3];
    const float* Wk = (const float*)d_in[4];
    const float* Wv = (const float*)d_in[5];
    const float* Wo = (const float*)d_in[6];
    const float* qw = (const float*)d_in[7];
    const float* kw = (const float*)d_in[8];
    float* out = (float*)d_out;

    void *pq, *pk, *pv, *po;
    cudaGetSymbolAddress(&pq, g_q);
    cudaGetSymbolAddress(&pk, g_k);
    cudaGetSymbolAddress(&pv, g_v);
    cudaGetSymbolAddress(&po, g_o);
    float* Qb = (float*)pq;
    float* Kb = (float*)pk;
    float* Vb = (float*)pv;
    float* Ob = (float*)po;

    dim3 gg(D_ / 64, M_ / 64);   // (64, 8)

    sgemm64<<<gg, 256>>>(x, Wq, Qb, D_, D_);
    sgemm64<<<gg, 256>>>(x, Wk, Kb, D_, D_);
    sgemm64<<<gg, 256>>>(x, Wv, Vb, D_, D_);

    rmsnorm_k<<<(M_ * H_) / 8, 256>>>(Qb, qw);
    rmsnorm_k<<<(M_ * H_) / 8, 256>>>(Kb, kw);

    attn_kernel<<<dim3(L_ / 32, H_, B_), 256>>>(Qb, Kb, Vb, ck, cv, Ob);

    sgemm64<<<gg, 256>>>(Ob, Wo, out, D_, D_);
}

// round 2
// speedup vs baseline: 1.6880x; 1.6880x over previous
#include <cuda_runtime.h>

// Problem constants (fixed by setup_inputs)
constexpr int B_  = 2;
constexpr int L_  = 256;
constexpr int D_  = 4096;
constexpr int H_  = 32;
constexpr int Dh_ = 128;
constexpr int S_  = 4224;          // SINK + LOCAL
constexpr int SINK_ = 128;
constexpr int WINS_ = S_ - L_;     // 3968
constexpr int M_  = B_ * L_;       // 512 rows
constexpr int BK  = 16;

// Scratch (device globals: allocation-free)
__device__ float g_q[M_ * D_];
__device__ float g_k[M_ * D_];
__device__ float g_v[M_ * D_];
__device__ float g_o[M_ * D_];

typedef unsigned long long ull;

// ---- packed f32x2 helpers (FFMA2: ptxas won't emit from C++, PTX only) ----
__device__ __forceinline__ ull pk2(float x, float y) {
    ull r; asm("mov.b64 %0,{%1,%2};" : "=l"(r) : "f"(x), "f"(y)); return r;
}
__device__ __forceinline__ void upk2(ull v, float& x, float& y) {
    asm("mov.b64 {%0,%1},%2;" : "=f"(x), "=f"(y) : "l"(v));
}
__device__ __forceinline__ void fma2(ull& d, ull a, ull b) {
    asm("fma.rn.f32x2 %0,%1,%2,%0;" : "+l"(d) : "l"(a), "l"(b));
}
__device__ __forceinline__ void mul2(ull& d, ull a) {
    asm("mul.rn.f32x2 %0,%0,%1;" : "+l"(d) : "l"(a));
}

// ---------------------------------------------------------------------------
// SGEMM 128x128x16, 256 threads, 8x8 per thread, double-buffered, FFMA2.
// C[M,4096] = A[M,4096] @ W[4096,4096]. blockIdx.z selects (W,C) pair.
// ---------------------------------------------------------------------------
__global__ __launch_bounds__(256) void sgemm128(
    const float* __restrict__ A,
    const float* __restrict__ W0, const float* __restrict__ W1, const float* __restrict__ W2,
    float* __restrict__ C0, float* __restrict__ C1, float* __restrict__ C2)
{
    const float* W = (blockIdx.z == 0) ? W0 : (blockIdx.z == 1) ? W1 : W2;
    float*       C = (blockIdx.z == 0) ? C0 : (blockIdx.z == 1) ? C1 : C2;

    __shared__ float As[2][BK][132];   // [k][m], padded
    __shared__ float Bs[2][BK][128];   // [k][n]

    const int tid = threadIdx.x;
    const int tx  = tid & 15;          // n group
    const int ty  = tid >> 4;          // m group
    const int m0  = blockIdx.y * 128;
    const int n0  = blockIdx.x * 128;

    // loader mapping
    const int ra = tid & 127;          // A row in tile (0..127)
    const int ka = (tid >> 7) * 8;     // A k offset (0 or 8)
    const int rb = tid >> 4;           // W k row in tile (0..15)
    const int cb = (tid & 15) * 8;     // W col offset (0..120)

    const float* Ap = A + (long)(m0 + ra) * D_ + ka;
    const float* Wp = W + (long)rb * D_ + n0 + cb;

    ull acc[8][4];
#pragma unroll
    for (int i = 0; i < 8; ++i)
#pragma unroll
        for (int j = 0; j < 4; ++j) acc[i][j] = 0ull;

    // prologue: chunk 0
    float4 a0 = *(const float4*)(Ap);
    float4 a1 = *(const float4*)(Ap + 4);
    float4 b0 = *(const float4*)(Wp);
    float4 b1 = *(const float4*)(Wp + 4);
#pragma unroll
    for (int i = 0; i < 4; ++i) {
        As[0][ka + i][ra]     = ((float*)&a0)[i];
        As[0][ka + 4 + i][ra] = ((float*)&a1)[i];
    }
    *(float4*)&Bs[0][rb][cb]     = b0;
    *(float4*)&Bs[0][rb][cb + 4] = b1;
    __syncthreads();

    const int NCH = D_ / BK;  // 256
    for (int ch = 0; ch < NCH; ++ch) {
        const int cur = ch & 1, nxt = cur ^ 1;
        if (ch + 1 < NCH) {
            const float* Ap2 = Ap + (ch + 1) * BK;
            const float* Wp2 = Wp + (long)(ch + 1) * BK * D_;
            a0 = *(const float4*)(Ap2);
            a1 = *(const float4*)(Ap2 + 4);
            b0 = *(const float4*)(Wp2);
            b1 = *(const float4*)(Wp2 + 4);
        }
#pragma unroll
        for (int k = 0; k < BK; ++k) {
            float4 af0 = *(const float4*)&As[cur][k][ty * 8];
            float4 af1 = *(const float4*)&As[cur][k][ty * 8 + 4];
            ulonglong2 bf0 = *(const ulonglong2*)&Bs[cur][k][tx * 4];
            ulonglong2 bf1 = *(const ulonglong2*)&Bs[cur][k][64 + tx * 4];
            float am[8] = {af0.x, af0.y, af0.z, af0.w, af1.x, af1.y, af1.z, af1.w};
#pragma unroll
            for (int mi = 0; mi < 8; ++mi) {
                ull ap = pk2(am[mi], am[mi]);
                fma2(acc[mi][0], ap, bf0.x);
                fma2(acc[mi][1], ap, bf0.y);
                fma2(acc[mi][2], ap, bf1.x);
                fma2(acc[mi][3], ap, bf1.y);
            }
        }
        if (ch + 1 < NCH) {
#pragma unroll
            for (int i = 0; i < 4; ++i) {
                As[nxt][ka + i][ra]     = ((float*)&a0)[i];
                As[nxt][ka + 4 + i][ra] = ((float*)&a1)[i];
            }
            *(float4*)&Bs[nxt][rb][cb]     = b0;
            *(float4*)&Bs[nxt][rb][cb + 4] = b1;
        }
        __syncthreads();
    }

#pragma unroll
    for (int mi = 0; mi < 8; ++mi) {
        float4 r0, r1;
        upk2(acc[mi][0], r0.x, r0.y);
        upk2(acc[mi][1], r0.z, r0.w);
        upk2(acc[mi][2], r1.x, r1.y);
        upk2(acc[mi][3], r1.z, r1.w);
        float* cp = C + (long)(m0 + ty * 8 + mi) * D_ + n0;
        *(float4*)(cp + tx * 4)      = r0;
        *(float4*)(cp + 64 + tx * 4) = r1;
    }
}

// ---------------------------------------------------------------------------
// Per-head RMSNorm over Dh=128, one warp per row. X: [M*H, 128] in place.
// ---------------------------------------------------------------------------
__global__ __launch_bounds__(256) void rmsnorm_k(float* __restrict__ X,
                                                 const float* __restrict__ w) {
    const int row  = (blockIdx.x * 256 + threadIdx.x) >> 5;
    const int lane = threadIdx.x & 31;
    float* p = X + (long)row * 128 + lane * 4;
    float4 v = *(float4*)p;
    float ss = v.x * v.x + v.y * v.y + v.z * v.z + v.w * v.w;
#pragma unroll
    for (int o = 16; o; o >>= 1) ss += __shfl_xor_sync(0xffffffffu, ss, o);
    float r = rsqrtf(ss * (1.0f / 128.0f) + 1e-6f);
    float4 wv = *(const float4*)(w + lane * 4);
    v.x *= r * wv.x; v.y *= r * wv.y; v.z *= r * wv.z; v.w *= r * wv.w;
    *(float4*)p = v;
}

// ---------------------------------------------------------------------------
// Flash attention, FFMA2 + interleaved dim mapping (conflict-free LDS.128).
// Block: 256 threads, 32 queries. Grid: (L/32, H, B).
// Lane c = tid&7 owns dims {i*32 + c*4 .. +3} for i in 0..3 (permutation of Dh).
// ---------------------------------------------------------------------------
__global__ __launch_bounds__(256) void attn_kernel(const float* __restrict__ Q,
                                                   const float* __restrict__ Kn,
                                                   const float* __restrict__ Vn,
                                                   const float* __restrict__ cK,
                                                   const float* __restrict__ cV,
                                                   float* __restrict__ O) {
    __shared__ float Ks[32][128];
    __shared__ float Vs[32][128];

    const int tid = threadIdx.x;
    const int r   = tid >> 3;          // query row in tile / load row
    const int c   = tid & 7;           // lane within query group
    const int h   = blockIdx.y;
    const int b   = blockIdx.z;
    const int q0  = blockIdx.x * 32;
    const int qi  = q0 + r;
    const int lim_g = WINS_ + qi;

    const float scale = 0.08838834764831845f;  // 1/sqrt(128)

    // q pairs, interleaved mapping, pre-scaled
    ull qp[8];
    {
        const float* qptr = Q + ((long)(b * L_ + qi) * H_ + h) * Dh_;
#pragma unroll
        for (int i = 0; i < 4; ++i) {
            float4 v = *(const float4*)(qptr + i * 32 + c * 4);
            qp[2 * i]     = pk2(v.x * scale, v.y * scale);
            qp[2 * i + 1] = pk2(v.z * scale, v.w * scale);
        }
    }

    ull ov[8];
#pragma unroll
    for (int i = 0; i < 8; ++i) ov[i] = 0ull;
    float m = -1e30f, l = 0.0f;

    const int t_end = min(S_, WINS_ + q0 + 32);

    for (int t0 = 0; t0 < t_end; t0 += 32) {
        // ---- load K/V tile (row r, interleaved dims) ----
        {
            const int sg = t0 + r;
            const float *ksrc, *vsrc;
            if (sg < WINS_) {
                const int src = (sg < SINK_) ? sg : sg + L_;
                const long off = (((long)b * S_ + src) * H_ + h) * Dh_;
                ksrc = cK + off; vsrc = cV + off;
            } else {
                const long off = (((long)b * L_ + (sg - WINS_)) * H_ + h) * Dh_;
                ksrc = Kn + off; vsrc = Vn + off;
            }
#pragma unroll
            for (int i = 0; i < 4; ++i) {
                const int d = i * 32 + c * 4;
                *(float4*)&Ks[r][d] = *(const float4*)(ksrc + d);
                *(float4*)&Vs[r][d] = *(const float4*)(vsrc + d);
            }
        }
        __syncthreads();

        // ---- logits ----
        float p[32];
#pragma unroll
        for (int j = 0; j < 32; ++j) {
            ulonglong2 k0 = *(const ulonglong2*)&Ks[j][c * 4];
            ulonglong2 k1 = *(const ulonglong2*)&Ks[j][32 + c * 4];
            ulonglong2 k2 = *(const ulonglong2*)&Ks[j][64 + c * 4];
            ulonglong2 k3 = *(const ulonglong2*)&Ks[j][96 + c * 4];
            ull s = 0ull;
            fma2(s, qp[0], k0.x); fma2(s, qp[1], k0.y);
            fma2(s, qp[2], k1.x); fma2(s, qp[3], k1.y);
            fma2(s, qp[4], k2.x); fma2(s, qp[5], k2.y);
            fma2(s, qp[6], k3.x); fma2(s, qp[7], k3.y);
            float sx, sy; upk2(s, sx, sy);
            float acc = sx + sy;
            acc += __shfl_xor_sync(0xffffffffu, acc, 1);
            acc += __shfl_xor_sync(0xffffffffu, acc, 2);
            acc += __shfl_xor_sync(0xffffffffu, acc, 4);
            p[j] = (t0 + j <= lim_g) ? acc : -1e30f;
        }

        // ---- online softmax ----
        float mt = m;
#pragma unroll
        for (int j = 0; j < 32; ++j) mt = fmaxf(mt, p[j]);
        const float alpha = __expf(m - mt);
        m = mt;
        float ls = 0.0f;
#pragma unroll
        for (int j = 0; j < 32; ++j) { p[j] = __expf(p[j] - mt); ls += p[j]; }
        l = l * alpha + ls;
        {
            ull al = pk2(alpha, alpha);
#pragma unroll
            for (int i = 0; i < 8; ++i) mul2(ov[i], al);
        }

        // ---- P @ V ----
#pragma unroll
        for (int j = 0; j < 32; ++j) {
            ull pj = pk2(p[j], p[j]);
            ulonglong2 v0 = *(const ulonglong2*)&Vs[j][c * 4];
            ulonglong2 v1 = *(const ulonglong2*)&Vs[j][32 + c * 4];
            ulonglong2 v2 = *(const ulonglong2*)&Vs[j][64 + c * 4];
            ulonglong2 v3 = *(const ulonglong2*)&Vs[j][96 + c * 4];
            fma2(ov[0], pj, v0.x); fma2(ov[1], pj, v0.y);
            fma2(ov[2], pj, v1.x); fma2(ov[3], pj, v1.y);
            fma2(ov[4], pj, v2.x); fma2(ov[5], pj, v2.y);
            fma2(ov[6], pj, v3.x); fma2(ov[7], pj, v3.y);
        }
        __syncthreads();
    }

    const float inv = 1.0f / l;
    float* op = O + ((long)(b * L_ + qi) * H_ + h) * Dh_;
#pragma unroll
    for (int i = 0; i < 4; ++i) {
        float4 v;
        upk2(ov[2 * i],     v.x, v.y);
        upk2(ov[2 * i + 1], v.z, v.w);
        v.x *= inv; v.y *= inv; v.z *= inv; v.w *= inv;
        *(float4*)(op + i * 32 + c * 4) = v;
    }
}

// ---------------------------------------------------------------------------
extern "C" void kernel_launch(void* const* d_in, const int* in_sizes, int n_in,
                              void* d_out, int out_size) {
    const float* x  = (const float*)d_in[0];
    const float* ck = (const float*)d_in[1];
    const float* cv = (const float*)d_in[2];
    const float* Wq = (const float*)d_in[3];
    const float* Wk = (const float*)d_in[4];
    const float* Wv = (const float*)d_in[5];
    const float* Wo = (const float*)d_in[6];
    const float* qw = (const float*)d_in[7];
    const float* kw = (const float*)d_in[8];
    float* out = (float*)d_out;

    void *pq, *pk, *pv, *po;
    cudaGetSymbolAddress(&pq, g_q);
    cudaGetSymbolAddress(&pk, g_k);
    cudaGetSymbolAddress(&pv, g_v);
    cudaGetSymbolAddress(&po, g_o);
    float* Qb = (float*)pq;
    float* Kb = (float*)pk;
    float* Vb = (float*)pv;
    float* Ob = (float*)po;

    // fused QKV projection: grid z selects W / output
    sgemm128<<<dim3(D_ / 128, M_ / 128, 3), 256>>>(x, Wq, Wk, Wv, Qb, Kb, Vb);

    rmsnorm_k<<<(M_ * H_) / 8, 256>>>(Qb, qw);
    rmsnorm_k<<<(M_ * H_) / 8, 256>>>(Kb, kw);

    attn_kernel<<<dim3(L_ / 32, H_, B_), 256>>>(Qb, Kb, Vb, ck, cv, Ob);

    // output projection
    sgemm128<<<dim3(D_ / 128, M_ / 128, 1), 256>>>(Ob, Wo, Wo, Wo, out, out, out);
}

// round 5
// speedup vs baseline: 2.9998x; 1.7771x over previous
#include <cuda_runtime.h>
#include <cuda_bf16.h>
#include <cstdint>

// Problem constants
constexpr int B_  = 2;
constexpr int L_  = 256;
constexpr int D_  = 4096;
constexpr int H_  = 32;
constexpr int Dh_ = 128;
constexpr int S_  = 4224;
constexpr int SINK_ = 128;
constexpr int WINS_ = S_ - L_;     // 3968
constexpr int M_  = B_ * L_;       // 512

// GEMM tiling
constexpr int BK = 32;
constexpr int NCHUNK = D_ / BK;        // 128
constexpr int A_ROW_B = 80;            // padded A smem row (32 bf16 -> 80B)
constexpr int B_ROW_B = 272;           // padded B smem row (128 bf16 -> 272B)
constexpr int A_TILE = 128 * A_ROW_B;  // 10240
constexpr int B_TILE = BK * B_ROW_B;   // 8704
constexpr int STAGE  = 2 * A_TILE + 2 * B_TILE;  // Ah,Al,Bh,Bl = 37888
constexpr int SMEMT  = 2 * STAGE;      // 75776

__device__ float g_q[M_ * D_];
__device__ float g_k[M_ * D_];
__device__ float g_v[M_ * D_];
__device__ float g_o[M_ * D_];

typedef unsigned long long ull;

// ---- helpers ----
__device__ __forceinline__ uint32_t smem_u32(const void* p) {
    uint32_t a;
    asm("{ .reg .u64 t; cvta.to.shared.u64 t, %1; cvt.u32.u64 %0, t; }" : "=r"(a) : "l"(p));
    return a;
}
__device__ __forceinline__ void ldsm4(uint32_t* r, uint32_t a) {
    asm volatile("ldmatrix.sync.aligned.m8n8.x4.shared.b16 {%0,%1,%2,%3},[%4];"
                 : "=r"(r[0]), "=r"(r[1]), "=r"(r[2]), "=r"(r[3]) : "r"(a));
}
__device__ __forceinline__ void ldsm4t(uint32_t* r, uint32_t a) {
    asm volatile("ldmatrix.sync.aligned.m8n8.x4.trans.shared.b16 {%0,%1,%2,%3},[%4];"
                 : "=r"(r[0]), "=r"(r[1]), "=r"(r[2]), "=r"(r[3]) : "r"(a));
}
__device__ __forceinline__ void mma_bf(float* c, const uint32_t* a, uint32_t b0, uint32_t b1) {
    asm volatile(
        "mma.sync.aligned.m16n8k16.row.col.f32.bf16.bf16.f32 "
        "{%0,%1,%2,%3},{%4,%5,%6,%7},{%8,%9},{%0,%1,%2,%3};"
        : "+f"(c[0]), "+f"(c[1]), "+f"(c[2]), "+f"(c[3])
        : "r"(a[0]), "r"(a[1]), "r"(a[2]), "r"(a[3]), "r"(b0), "r"(b1));
}
__device__ __forceinline__ void split2(float x, float y, uint32_t& hi, uint32_t& lo) {
    __nv_bfloat16 hx = __float2bfloat16_rn(x);
    __nv_bfloat16 hy = __float2bfloat16_rn(y);
    __nv_bfloat16 lx = __float2bfloat16_rn(x - __bfloat162float(hx));
    __nv_bfloat16 ly = __float2bfloat16_rn(y - __bfloat162float(hy));
    hi = (uint32_t)__bfloat16_as_ushort(hx) | ((uint32_t)__bfloat16_as_ushort(hy) << 16);
    lo = (uint32_t)__bfloat16_as_ushort(lx) | ((uint32_t)__bfloat16_as_ushort(ly) << 16);
}

// ---- packed f32x2 (attention) ----
__device__ __forceinline__ ull pk2(float x, float y) {
    ull r; asm("mov.b64 %0,{%1,%2};" : "=l"(r) : "f"(x), "f"(y)); return r;
}
__device__ __forceinline__ void upk2(ull v, float& x, float& y) {
    asm("mov.b64 {%0,%1},%2;" : "=f"(x), "=f"(y) : "l"(v));
}
__device__ __forceinline__ void fma2(ull& d, ull a, ull b) {
    asm("fma.rn.f32x2 %0,%1,%2,%0;" : "+l"(d) : "l"(a), "l"(b));
}
__device__ __forceinline__ void mul2(ull& d, ull a) {
    asm("mul.rn.f32x2 %0,%0,%1;" : "+l"(d) : "l"(a));
}

// ---------------------------------------------------------------------------
// mma.sync split-bf16 GEMM: C[M,4096] = A[M,4096] @ W[4096,4096]
// CTA 128x128xBK32, 8 warps (2m x 4n), warp tile 64x32, grid (N/128, M/128, z)
// ---------------------------------------------------------------------------
__global__ __launch_bounds__(256) void gemm_mma(
    const float* __restrict__ A,
    const float* __restrict__ W0, const float* __restrict__ W1, const float* __restrict__ W2,
    float* __restrict__ C0, float* __restrict__ C1, float* __restrict__ C2)
{
    const float* W = (blockIdx.z == 0) ? W0 : (blockIdx.z == 1) ? W1 : W2;
    float*       C = (blockIdx.z == 0) ? C0 : (blockIdx.z == 1) ? C1 : C2;

    extern __shared__ char smem[];
    const uint32_t sb = smem_u32(smem);
    const int tid  = threadIdx.x;
    const int wid  = tid >> 5;
    const int lane = tid & 31;
    const int wm   = wid & 1;          // m64 block
    const int wn   = wid >> 1;         // n32 block

    const int m0 = blockIdx.y * 128;
    const int n0 = blockIdx.x * 128;

    // loader maps
    const int arow = tid >> 1;             // 0..127
    const int ak0  = (tid & 1) * 16;       // 0 or 16
    const int brow = tid >> 3;             // 0..31
    const int bn0  = (tid & 7) * 16;       // 0..112

    const float* Ag = A + (long)(m0 + arow) * D_ + ak0;
    const float* Wg = W + (long)brow * D_ + n0 + bn0;

    float4 areg[4], breg[4];
#pragma unroll
    for (int i = 0; i < 4; ++i) {
        areg[i] = *(const float4*)(Ag + 4 * i);
        breg[i] = *(const float4*)(Wg + 4 * i);
    }

    float acc[4][4][4];
#pragma unroll
    for (int mt = 0; mt < 4; ++mt)
#pragma unroll
        for (int nt = 0; nt < 4; ++nt)
#pragma unroll
            for (int e = 0; e < 4; ++e) acc[mt][nt][e] = 0.0f;

    // ldmatrix per-lane address components (byte units)
    const int a_r   = (lane & 7) + ((lane >> 3) & 1) * 8;   // row within m16
    const int a_kb  = (lane >> 4) * 16;                      // k-byte within k16
    const int b_kr  = (lane & 7) + (lane >> 4) * 8;          // k row within k16
    const int b_nb  = ((lane >> 3) & 1) * 16;                // n-byte offset (8 bf16)

    for (int ch = 0; ch < NCHUNK; ++ch) {
        const int s = ch & 1;
        char* st = smem + s * STAGE;

        // ---- convert + store A (hi/lo) ----
        {
            uint32_t off = (uint32_t)(arow * A_ROW_B + ak0 * 2);
#pragma unroll
            for (int i = 0; i < 4; ++i) {
                uint32_t h0, l0, h1, l1;
                split2(areg[i].x, areg[i].y, h0, l0);
                split2(areg[i].z, areg[i].w, h1, l1);
                *(uint2*)(st + off + 8 * i)          = make_uint2(h0, h1);
                *(uint2*)(st + A_TILE + off + 8 * i) = make_uint2(l0, l1);
            }
        }
        // ---- convert + store B (hi/lo) ----
        {
            uint32_t off = (uint32_t)(2 * A_TILE + brow * B_ROW_B + bn0 * 2);
#pragma unroll
            for (int i = 0; i < 4; ++i) {
                uint32_t h0, l0, h1, l1;
                split2(breg[i].x, breg[i].y, h0, l0);
                split2(breg[i].z, breg[i].w, h1, l1);
                *(uint2*)(st + off + 8 * i)          = make_uint2(h0, h1);
                *(uint2*)(st + B_TILE + off + 8 * i) = make_uint2(l0, l1);
            }
        }
        __syncthreads();

        // ---- preload next chunk ----
        if (ch + 1 < NCHUNK) {
            const float* Ap = Ag + (ch + 1) * BK;
            const float* Wp = Wg + (long)(ch + 1) * BK * D_;
#pragma unroll
            for (int i = 0; i < 4; ++i) {
                areg[i] = *(const float4*)(Ap + 4 * i);
                breg[i] = *(const float4*)(Wp + 4 * i);
            }
        }

        // ---- MMAs over this stage ----
        const uint32_t Ah = sb + s * STAGE;
        const uint32_t Al = Ah + A_TILE;
        const uint32_t Bh = Ah + 2 * A_TILE;
        const uint32_t Bl = Bh + B_TILE;

#pragma unroll
        for (int kc = 0; kc < 2; ++kc) {
            uint32_t ah[4][4], al[4][4];
            uint32_t bh[4][2], bl[4][2];
            const uint32_t a_addr = (uint32_t)((wm * 64 + a_r) * A_ROW_B + kc * 32 + a_kb);
#pragma unroll
            for (int mt = 0; mt < 4; ++mt) {
                ldsm4(ah[mt], Ah + a_addr + mt * 16 * A_ROW_B);
                ldsm4(al[mt], Al + a_addr + mt * 16 * A_ROW_B);
            }
            // FIX: b_nb is already a byte offset — do not scale by 2.
            const uint32_t b_addr = (uint32_t)((kc * 16 + b_kr) * B_ROW_B + (wn * 32) * 2 + b_nb);
#pragma unroll
            for (int p = 0; p < 2; ++p) {
                uint32_t rh[4], rl[4];
                ldsm4t(rh, Bh + b_addr + p * 32);
                ldsm4t(rl, Bl + b_addr + p * 32);
                bh[2 * p][0] = rh[0]; bh[2 * p][1] = rh[2];
                bh[2 * p + 1][0] = rh[1]; bh[2 * p + 1][1] = rh[3];
                bl[2 * p][0] = rl[0]; bl[2 * p][1] = rl[2];
                bl[2 * p + 1][0] = rl[1]; bl[2 * p + 1][1] = rl[3];
            }
#pragma unroll
            for (int mt = 0; mt < 4; ++mt)
#pragma unroll
                for (int nt = 0; nt < 4; ++nt) {
                    mma_bf(acc[mt][nt], ah[mt], bh[nt][0], bh[nt][1]);
                    mma_bf(acc[mt][nt], ah[mt], bl[nt][0], bl[nt][1]);
                    mma_bf(acc[mt][nt], al[mt], bh[nt][0], bh[nt][1]);
                }
        }
        __syncthreads();
    }

    // ---- epilogue ----
    const int gr = lane >> 2;
    const int gc = lane & 3;
#pragma unroll
    for (int mt = 0; mt < 4; ++mt) {
        const int row = m0 + wm * 64 + mt * 16 + gr;
        float* c0 = C + (long)row * D_ + n0 + wn * 32;
        float* c1 = C + (long)(row + 8) * D_ + n0 + wn * 32;
#pragma unroll
        for (int nt = 0; nt < 4; ++nt) {
            *(float2*)(c0 + nt * 8 + gc * 2) = make_float2(acc[mt][nt][0], acc[mt][nt][1]);
            *(float2*)(c1 + nt * 8 + gc * 2) = make_float2(acc[mt][nt][2], acc[mt][nt][3]);
        }
    }
}

// ---------------------------------------------------------------------------
__global__ __launch_bounds__(256) void rmsnorm_k(float* __restrict__ X,
                                                 const float* __restrict__ w) {
    const int row  = (blockIdx.x * 256 + threadIdx.x) >> 5;
    const int lane = threadIdx.x & 31;
    float* p = X + (long)row * 128 + lane * 4;
    float4 v = *(float4*)p;
    float ss = v.x * v.x + v.y * v.y + v.z * v.z + v.w * v.w;
#pragma unroll
    for (int o = 16; o; o >>= 1) ss += __shfl_xor_sync(0xffffffffu, ss, o);
    float r = rsqrtf(ss * (1.0f / 128.0f) + 1e-6f);
    float4 wv = *(const float4*)(w + lane * 4);
    v.x *= r * wv.x; v.y *= r * wv.y; v.z *= r * wv.z; v.w *= r * wv.w;
    *(float4*)p = v;
}

// ---------------------------------------------------------------------------
// Flash attention (FFMA2, interleaved dims)
// ---------------------------------------------------------------------------
__global__ __launch_bounds__(256) void attn_kernel(const float* __restrict__ Q,
                                                   const float* __restrict__ Kn,
                                                   const float* __restrict__ Vn,
                                                   const float* __restrict__ cK,
                                                   const float* __restrict__ cV,
                                                   float* __restrict__ O) {
    __shared__ float Ks[32][128];
    __shared__ float Vs[32][128];

    const int tid = threadIdx.x;
    const int r   = tid >> 3;
    const int c   = tid & 7;
    const int h   = blockIdx.y;
    const int b   = blockIdx.z;
    const int q0  = blockIdx.x * 32;
    const int qi  = q0 + r;
    const int lim_g = WINS_ + qi;

    const float scale = 0.08838834764831845f;

    ull qp[8];
    {
        const float* qptr = Q + ((long)(b * L_ + qi) * H_ + h) * Dh_;
#pragma unroll
        for (int i = 0; i < 4; ++i) {
            float4 v = *(const float4*)(qptr + i * 32 + c * 4);
            qp[2 * i]     = pk2(v.x * scale, v.y * scale);
            qp[2 * i + 1] = pk2(v.z * scale, v.w * scale);
        }
    }

    ull ov[8];
#pragma unroll
    for (int i = 0; i < 8; ++i) ov[i] = 0ull;
    float m = -1e30f, l = 0.0f;

    const int t_end = min(S_, WINS_ + q0 + 32);

    for (int t0 = 0; t0 < t_end; t0 += 32) {
        {
            const int sg = t0 + r;
            const float *ksrc, *vsrc;
            if (sg < WINS_) {
                const int src = (sg < SINK_) ? sg : sg + L_;
                const long off = (((long)b * S_ + src) * H_ + h) * Dh_;
                ksrc = cK + off; vsrc = cV + off;
            } else {
                const long off = (((long)b * L_ + (sg - WINS_)) * H_ + h) * Dh_;
                ksrc = Kn + off; vsrc = Vn + off;
            }
#pragma unroll
            for (int i = 0; i < 4; ++i) {
                const int d = i * 32 + c * 4;
                *(float4*)&Ks[r][d] = *(const float4*)(ksrc + d);
                *(float4*)&Vs[r][d] = *(const float4*)(vsrc + d);
            }
        }
        __syncthreads();

        float p[32];
#pragma unroll
        for (int j = 0; j < 32; ++j) {
            ulonglong2 k0 = *(const ulonglong2*)&Ks[j][c * 4];
            ulonglong2 k1 = *(const ulonglong2*)&Ks[j][32 + c * 4];
            ulonglong2 k2 = *(const ulonglong2*)&Ks[j][64 + c * 4];
            ulonglong2 k3 = *(const ulonglong2*)&Ks[j][96 + c * 4];
            ull s = 0ull;
            fma2(s, qp[0], k0.x); fma2(s, qp[1], k0.y);
            fma2(s, qp[2], k1.x); fma2(s, qp[3], k1.y);
            fma2(s, qp[4], k2.x); fma2(s, qp[5], k2.y);
            fma2(s, qp[6], k3.x); fma2(s, qp[7], k3.y);
            float sx, sy; upk2(s, sx, sy);
            float acc = sx + sy;
            acc += __shfl_xor_sync(0xffffffffu, acc, 1);
            acc += __shfl_xor_sync(0xffffffffu, acc, 2);
            acc += __shfl_xor_sync(0xffffffffu, acc, 4);
            p[j] = (t0 + j <= lim_g) ? acc : -1e30f;
        }

        float mt = m;
#pragma unroll
        for (int j = 0; j < 32; ++j) mt = fmaxf(mt, p[j]);
        const float alpha = __expf(m - mt);
        m = mt;
        float ls = 0.0f;
#pragma unroll
        for (int j = 0; j < 32; ++j) { p[j] = __expf(p[j] - mt); ls += p[j]; }
        l = l * alpha + ls;
        {
            ull al = pk2(alpha, alpha);
#pragma unroll
            for (int i = 0; i < 8; ++i) mul2(ov[i], al);
        }

#pragma unroll
        for (int j = 0; j < 32; ++j) {
            ull pj = pk2(p[j], p[j]);
            ulonglong2 v0 = *(const ulonglong2*)&Vs[j][c * 4];
            ulonglong2 v1 = *(const ulonglong2*)&Vs[j][32 + c * 4];
            ulonglong2 v2 = *(const ulonglong2*)&Vs[j][64 + c * 4];
            ulonglong2 v3 = *(const ulonglong2*)&Vs[j][96 + c * 4];
            fma2(ov[0], pj, v0.x); fma2(ov[1], pj, v0.y);
            fma2(ov[2], pj, v1.x); fma2(ov[3], pj, v1.y);
            fma2(ov[4], pj, v2.x); fma2(ov[5], pj, v2.y);
            fma2(ov[6], pj, v3.x); fma2(ov[7], pj, v3.y);
        }
        __syncthreads();
    }

    const float inv = 1.0f / l;
    float* op = O + ((long)(b * L_ + qi) * H_ + h) * Dh_;
#pragma unroll
    for (int i = 0; i < 4; ++i) {
        float4 v;
        upk2(ov[2 * i],     v.x, v.y);
        upk2(ov[2 * i + 1], v.z, v.w);
        v.x *= inv; v.y *= inv; v.z *= inv; v.w *= inv;
        *(float4*)(op + i * 32 + c * 4) = v;
    }
}

// ---------------------------------------------------------------------------
extern "C" void kernel_launch(void* const* d_in, const int* in_sizes, int n_in,
                              void* d_out, int out_size) {
    const float* x  = (const float*)d_in[0];
    const float* ck = (const float*)d_in[1];
    const float* cv = (const float*)d_in[2];
    const float* Wq = (const float*)d_in[3];
    const float* Wk = (const float*)d_in[4];
    const float* Wv = (const float*)d_in[5];
    const float* Wo = (const float*)d_in[6];
    const float* qw = (const float*)d_in[7];
    const float* kw = (const float*)d_in[8];
    float* out = (float*)d_out;

    void *pq, *pk, *pv, *po;
    cudaGetSymbolAddress(&pq, g_q);
    cudaGetSymbolAddress(&pk, g_k);
    cudaGetSymbolAddress(&pv, g_v);
    cudaGetSymbolAddress(&po, g_o);
    float* Qb = (float*)pq;
    float* Kb = (float*)pk;
    float* Vb = (float*)pv;
    float* Ob = (float*)po;

    cudaFuncSetAttribute(gemm_mma, cudaFuncAttributeMaxDynamicSharedMemorySize, SMEMT);

    // fused QKV projection (tensor cores via mma.sync)
    gemm_mma<<<dim3(D_ / 128, M_ / 128, 3), 256, SMEMT>>>(x, Wq, Wk, Wv, Qb, Kb, Vb);

    rmsnorm_k<<<(M_ * H_) / 8, 256>>>(Qb, qw);
    rmsnorm_k<<<(M_ * H_) / 8, 256>>>(Kb, kw);

    attn_kernel<<<dim3(L_ / 32, H_, B_), 256>>>(Qb, Kb, Vb, ck, cv, Ob);

    // output projection
    gemm_mma<<<dim3(D_ / 128, M_ / 128, 1), 256, SMEMT>>>(Ob, Wo, Wo, Wo, out, out, out);
}

// round 6
// speedup vs baseline: 3.4326x; 1.1443x over previous
#include <cuda_runtime.h>
#include <cuda_bf16.h>
#include <cstdint>

// Problem constants
constexpr int B_  = 2;
constexpr int L_  = 256;
constexpr int D_  = 4096;
constexpr int H_  = 32;
constexpr int Dh_ = 128;
constexpr int S_  = 4224;
constexpr int SINK_ = 128;
constexpr int WINS_ = S_ - L_;     // 3968
constexpr int M_  = B_ * L_;       // 512
constexpr size_t DD = (size_t)D_ * D_;

// GEMM tiling
constexpr int BK = 32;
constexpr int NCHUNK = D_ / BK;        // 128
constexpr int A_ROW_B = 80;            // padded A smem row (32 bf16 -> 80B)
constexpr int B_ROW_B = 272;           // padded B smem row (128 bf16 -> 272B)
constexpr int A_TILE = 128 * A_ROW_B;  // 10240
constexpr int B_TILE = BK * B_ROW_B;   // 8704
constexpr int STAGE  = 2 * A_TILE + 2 * B_TILE;  // 37888
constexpr int SMEMT  = 2 * STAGE;      // 75776

// scratch
__device__ float g_q[M_ * D_];
__device__ float g_k[M_ * D_];
__device__ float g_v[M_ * D_];
__device__ float g_o[M_ * D_];
__device__ __nv_bfloat16 g_whi[4 * DD];
__device__ __nv_bfloat16 g_wlo[4 * DD];
__device__ __nv_bfloat16 g_xhi[M_ * D_];
__device__ __nv_bfloat16 g_xlo[M_ * D_];
__device__ __nv_bfloat16 g_ohi[M_ * D_];
__device__ __nv_bfloat16 g_olo[M_ * D_];

typedef unsigned long long ull;

// ---- helpers ----
__device__ __forceinline__ uint32_t smem_u32(const void* p) {
    uint32_t a;
    asm("{ .reg .u64 t; cvta.to.shared.u64 t, %1; cvt.u32.u64 %0, t; }" : "=r"(a) : "l"(p));
    return a;
}
__device__ __forceinline__ void ldsm4(uint32_t* r, uint32_t a) {
    asm volatile("ldmatrix.sync.aligned.m8n8.x4.shared.b16 {%0,%1,%2,%3},[%4];"
                 : "=r"(r[0]), "=r"(r[1]), "=r"(r[2]), "=r"(r[3]) : "r"(a));
}
__device__ __forceinline__ void ldsm4t(uint32_t* r, uint32_t a) {
    asm volatile("ldmatrix.sync.aligned.m8n8.x4.trans.shared.b16 {%0,%1,%2,%3},[%4];"
                 : "=r"(r[0]), "=r"(r[1]), "=r"(r[2]), "=r"(r[3]) : "r"(a));
}
__device__ __forceinline__ void mma_bf(float* c, const uint32_t* a, uint32_t b0, uint32_t b1) {
    asm volatile(
        "mma.sync.aligned.m16n8k16.row.col.f32.bf16.bf16.f32 "
        "{%0,%1,%2,%3},{%4,%5,%6,%7},{%8,%9},{%0,%1,%2,%3};"
        : "+f"(c[0]), "+f"(c[1]), "+f"(c[2]), "+f"(c[3])
        : "r"(a[0]), "r"(a[1]), "r"(a[2]), "r"(a[3]), "r"(b0), "r"(b1));
}
__device__ __forceinline__ void split2(float x, float y, uint32_t& hi, uint32_t& lo) {
    __nv_bfloat16 hx = __float2bfloat16_rn(x);
    __nv_bfloat16 hy = __float2bfloat16_rn(y);
    __nv_bfloat16 lx = __float2bfloat16_rn(x - __bfloat162float(hx));
    __nv_bfloat16 ly = __float2bfloat16_rn(y - __bfloat162float(hy));
    hi = (uint32_t)__bfloat16_as_ushort(hx) | ((uint32_t)__bfloat16_as_ushort(hy) << 16);
    lo = (uint32_t)__bfloat16_as_ushort(lx) | ((uint32_t)__bfloat16_as_ushort(ly) << 16);
}
__device__ __forceinline__ void cpa16(uint32_t dst, const void* src) {
    asm volatile("cp.async.ca.shared.global [%0],[%1],16;" :: "r"(dst), "l"(src));
}
__device__ __forceinline__ void cpa_commit() {
    asm volatile("cp.async.commit_group;" ::: "memory");
}
__device__ __forceinline__ void cpa_wait1() {
    asm volatile("cp.async.wait_group 1;" ::: "memory");
}
__device__ __forceinline__ void cpa_wait0() {
    asm volatile("cp.async.wait_group 0;" ::: "memory");
}

// ---- packed f32x2 (attention) ----
__device__ __forceinline__ ull pk2(float x, float y) {
    ull r; asm("mov.b64 %0,{%1,%2};" : "=l"(r) : "f"(x), "f"(y)); return r;
}
__device__ __forceinline__ void upk2(ull v, float& x, float& y) {
    asm("mov.b64 {%0,%1},%2;" : "=f"(x), "=f"(y) : "l"(v));
}
__device__ __forceinline__ void fma2(ull& d, ull a, ull b) {
    asm("fma.rn.f32x2 %0,%1,%2,%0;" : "+l"(d) : "l"(a), "l"(b));
}
__device__ __forceinline__ void mul2(ull& d, ull a) {
    asm("mul.rn.f32x2 %0,%0,%1;" : "+l"(d) : "l"(a));
}

// ---------------------------------------------------------------------------
// Split-convert kernels: fp32 -> (hi, lo) bf16
// ---------------------------------------------------------------------------
__global__ __launch_bounds__(256) void cvt_w(
    const float* __restrict__ w0, const float* __restrict__ w1,
    const float* __restrict__ w2, const float* __restrict__ w3,
    __nv_bfloat16* __restrict__ hi, __nv_bfloat16* __restrict__ lo)
{
    const float* src = (blockIdx.y == 0) ? w0 : (blockIdx.y == 1) ? w1 : (blockIdx.y == 2) ? w2 : w3;
    const size_t base = (size_t)blockIdx.y * DD;
    const size_t i = ((size_t)blockIdx.x * 256 + threadIdx.x) * 8;
    float4 f0 = *(const float4*)(src + i);
    float4 f1 = *(const float4*)(src + i + 4);
    uint4 h, l;
    split2(f0.x, f0.y, h.x, l.x);
    split2(f0.z, f0.w, h.y, l.y);
    split2(f1.x, f1.y, h.z, l.z);
    split2(f1.z, f1.w, h.w, l.w);
    *(uint4*)(hi + base + i) = h;
    *(uint4*)(lo + base + i) = l;
}

__global__ __launch_bounds__(256) void cvt_x(
    const float* __restrict__ src,
    __nv_bfloat16* __restrict__ hi, __nv_bfloat16* __restrict__ lo)
{
    const size_t i = ((size_t)blockIdx.x * 256 + threadIdx.x) * 8;
    float4 f0 = *(const float4*)(src + i);
    float4 f1 = *(const float4*)(src + i + 4);
    uint4 h, l;
    split2(f0.x, f0.y, h.x, l.x);
    split2(f0.z, f0.w, h.y, l.y);
    split2(f1.x, f1.y, h.z, l.z);
    split2(f1.z, f1.w, h.w, l.w);
    *(uint4*)(hi + i) = h;
    *(uint4*)(lo + i) = l;
}

// ---------------------------------------------------------------------------
// mma.sync split-bf16 GEMM, pre-converted inputs, cp.async double-buffer.
// C[M,4096] = A[M,4096] @ W[4096,4096]. grid (N/128, M/128, z)
// ---------------------------------------------------------------------------
__global__ __launch_bounds__(256) void gemm_mma(
    const __nv_bfloat16* __restrict__ Ahi, const __nv_bfloat16* __restrict__ Alo,
    const __nv_bfloat16* __restrict__ Whi, const __nv_bfloat16* __restrict__ Wlo,
    int wzoff,
    float* __restrict__ C0, float* __restrict__ C1, float* __restrict__ C2)
{
    float* C = (blockIdx.z == 0) ? C0 : (blockIdx.z == 1) ? C1 : C2;
    const size_t woff = (size_t)(blockIdx.z + wzoff) * DD;

    extern __shared__ char smem[];
    const uint32_t sb = smem_u32(smem);
    const int tid  = threadIdx.x;
    const int wid  = tid >> 5;
    const int lane = tid & 31;
    const int wm   = wid & 1;
    const int wn   = wid >> 1;

    const int m0 = blockIdx.y * 128;
    const int n0 = blockIdx.x * 128;

    // cp.async chunk maps (each thread: 2 chunks per tile, 8 total per stage)
    const int acr = tid >> 1;              // A chunk row   (two chunks: tid*2, tid*2+1 -> rows tid>>1? no)
    // A: 512 chunks: c = tid*2 + i; row = c>>2 (0..127), kc16 = c&3
    // B: 512 chunks: c = tid*2 + i; row = c>>4 (0..31),  nc16 = c&15

    const __nv_bfloat16* AhiB = Ahi + (size_t)m0 * D_;
    const __nv_bfloat16* AloB = Alo + (size_t)m0 * D_;
    const __nv_bfloat16* WhiB = Whi + woff + n0;
    const __nv_bfloat16* WloB = Wlo + woff + n0;

    float acc[4][4][4];
#pragma unroll
    for (int mt = 0; mt < 4; ++mt)
#pragma unroll
        for (int nt = 0; nt < 4; ++nt)
#pragma unroll
            for (int e = 0; e < 4; ++e) acc[mt][nt][e] = 0.0f;

    // ldmatrix per-lane address components (byte units)
    const int a_r   = (lane & 7) + ((lane >> 3) & 1) * 8;
    const int a_kb  = (lane >> 4) * 16;
    const int b_kr  = (lane & 7) + (lane >> 4) * 8;
    const int b_nb  = ((lane >> 3) & 1) * 16;

    auto issue_stage = [&](int ch, int s) {
        const uint32_t stA = sb + s * STAGE;
        const uint32_t stB = stA + 2 * A_TILE;
#pragma unroll
        for (int i = 0; i < 2; ++i) {
            const int c = tid * 2 + i;
            const int ar = c >> 2, akc = c & 3;
            const size_t aoff = (size_t)ar * D_ + ch * BK + akc * 8;
            const uint32_t adst = stA + ar * A_ROW_B + akc * 16;
            cpa16(adst, AhiB + aoff);
            cpa16(adst + A_TILE, AloB + aoff);
            const int br = c >> 4, bnc = c & 15;
            const size_t boff = (size_t)(ch * BK + br) * D_ + bnc * 8;
            const uint32_t bdst = stB + br * B_ROW_B + bnc * 16;
            cpa16(bdst, WhiB + boff);
            cpa16(bdst + B_TILE, WloB + boff);
        }
        cpa_commit();
    };

    issue_stage(0, 0);

    for (int ch = 0; ch < NCHUNK; ++ch) {
        const int s = ch & 1;
        if (ch + 1 < NCHUNK) { issue_stage(ch + 1, s ^ 1); cpa_wait1(); }
        else cpa_wait0();
        __syncthreads();

        const uint32_t Ah = sb + s * STAGE;
        const uint32_t Al = Ah + A_TILE;
        const uint32_t Bh = Ah + 2 * A_TILE;
        const uint32_t Bl = Bh + B_TILE;

#pragma unroll
        for (int kc = 0; kc < 2; ++kc) {
            uint32_t ah[4][4], al[4][4];
            uint32_t bh[4][2], bl[4][2];
            const uint32_t a_addr = (uint32_t)((wm * 64 + a_r) * A_ROW_B + kc * 32 + a_kb);
#pragma unroll
            for (int mt = 0; mt < 4; ++mt) {
                ldsm4(ah[mt], Ah + a_addr + mt * 16 * A_ROW_B);
                ldsm4(al[mt], Al + a_addr + mt * 16 * A_ROW_B);
            }
            const uint32_t b_addr = (uint32_t)((kc * 16 + b_kr) * B_ROW_B + (wn * 32) * 2 + b_nb);
#pragma unroll
            for (int p = 0; p < 2; ++p) {
                uint32_t rh[4], rl[4];
                ldsm4t(rh, Bh + b_addr + p * 32);
                ldsm4t(rl, Bl + b_addr + p * 32);
                bh[2 * p][0] = rh[0]; bh[2 * p][1] = rh[2];
                bh[2 * p + 1][0] = rh[1]; bh[2 * p + 1][1] = rh[3];
                bl[2 * p][0] = rl[0]; bl[2 * p][1] = rl[2];
                bl[2 * p + 1][0] = rl[1]; bl[2 * p + 1][1] = rl[3];
            }
#pragma unroll
            for (int mt = 0; mt < 4; ++mt)
#pragma unroll
                for (int nt = 0; nt < 4; ++nt) {
                    mma_bf(acc[mt][nt], ah[mt], bh[nt][0], bh[nt][1]);
                    mma_bf(acc[mt][nt], ah[mt], bl[nt][0], bl[nt][1]);
                    mma_bf(acc[mt][nt], al[mt], bh[nt][0], bh[nt][1]);
                }
        }
        __syncthreads();
    }

    // ---- epilogue ----
    const int gr = lane >> 2;
    const int gc = lane & 3;
#pragma unroll
    for (int mt = 0; mt < 4; ++mt) {
        const int row = m0 + wm * 64 + mt * 16 + gr;
        float* c0 = C + (size_t)row * D_ + n0 + wn * 32;
        float* c1 = C + (size_t)(row + 8) * D_ + n0 + wn * 32;
#pragma unroll
        for (int nt = 0; nt < 4; ++nt) {
            *(float2*)(c0 + nt * 8 + gc * 2) = make_float2(acc[mt][nt][0], acc[mt][nt][1]);
            *(float2*)(c1 + nt * 8 + gc * 2) = make_float2(acc[mt][nt][2], acc[mt][nt][3]);
        }
    }
}

// ---------------------------------------------------------------------------
__global__ __launch_bounds__(256) void rmsnorm_k(float* __restrict__ X,
                                                 const float* __restrict__ w) {
    const int row  = (blockIdx.x * 256 + threadIdx.x) >> 5;
    const int lane = threadIdx.x & 31;
    float* p = X + (size_t)row * 128 + lane * 4;
    float4 v = *(float4*)p;
    float ss = v.x * v.x + v.y * v.y + v.z * v.z + v.w * v.w;
#pragma unroll
    for (int o = 16; o; o >>= 1) ss += __shfl_xor_sync(0xffffffffu, ss, o);
    float r = rsqrtf(ss * (1.0f / 128.0f) + 1e-6f);
    float4 wv = *(const float4*)(w + lane * 4);
    v.x *= r * wv.x; v.y *= r * wv.y; v.z *= r * wv.z; v.w *= r * wv.w;
    *(float4*)p = v;
}

// ---------------------------------------------------------------------------
// Flash attention (FFMA2, interleaved dims), 16-key half-chunks, 2 CTAs/SM.
// ---------------------------------------------------------------------------
__global__ __launch_bounds__(256, 2) void attn_kernel(const float* __restrict__ Q,
                                                      const float* __restrict__ Kn,
                                                      const float* __restrict__ Vn,
                                                      const float* __restrict__ cK,
                                                      const float* __restrict__ cV,
                                                      float* __restrict__ O) {
    __shared__ float Ks[32][128];
    __shared__ float Vs[32][128];

    const int tid = threadIdx.x;
    const int r   = tid >> 3;
    const int c   = tid & 7;
    const int h   = blockIdx.y;
    const int b   = blockIdx.z;
    const int q0  = blockIdx.x * 32;
    const int qi  = q0 + r;
    const int lim_g = WINS_ + qi;

    const float scale = 0.08838834764831845f;

    ull qp[8];
    {
        const float* qptr = Q + ((size_t)(b * L_ + qi) * H_ + h) * Dh_;
#pragma unroll
        for (int i = 0; i < 4; ++i) {
            float4 v = *(const float4*)(qptr + i * 32 + c * 4);
            qp[2 * i]     = pk2(v.x * scale, v.y * scale);
            qp[2 * i + 1] = pk2(v.z * scale, v.w * scale);
        }
    }

    ull ov[8];
#pragma unroll
    for (int i = 0; i < 8; ++i) ov[i] = 0ull;
    float m = -1e30f, l = 0.0f;

    const int t_end = min(S_, WINS_ + q0 + 32);

    for (int t0 = 0; t0 < t_end; t0 += 32) {
        {
            const int sg = t0 + r;
            const float *ksrc, *vsrc;
            if (sg < WINS_) {
                const int src = (sg < SINK_) ? sg : sg + L_;
                const size_t off = (((size_t)b * S_ + src) * H_ + h) * Dh_;
                ksrc = cK + off; vsrc = cV + off;
            } else {
                const size_t off = (((size_t)b * L_ + (sg - WINS_)) * H_ + h) * Dh_;
                ksrc = Kn + off; vsrc = Vn + off;
            }
#pragma unroll
            for (int i = 0; i < 4; ++i) {
                const int d = i * 32 + c * 4;
                *(float4*)&Ks[r][d] = *(const float4*)(ksrc + d);
                *(float4*)&Vs[r][d] = *(const float4*)(vsrc + d);
            }
        }
        __syncthreads();

        const bool need_mask = (t0 + 31 > lim_g);

#pragma unroll
        for (int half = 0; half < 2; ++half) {
            float p[16];
#pragma unroll
            for (int jj = 0; jj < 16; ++jj) {
                const int j = half * 16 + jj;
                ulonglong2 k0 = *(const ulonglong2*)&Ks[j][c * 4];
                ulonglong2 k1 = *(const ulonglong2*)&Ks[j][32 + c * 4];
                ulonglong2 k2 = *(const ulonglong2*)&Ks[j][64 + c * 4];
                ulonglong2 k3 = *(const ulonglong2*)&Ks[j][96 + c * 4];
                ull s = 0ull;
                fma2(s, qp[0], k0.x); fma2(s, qp[1], k0.y);
                fma2(s, qp[2], k1.x); fma2(s, qp[3], k1.y);
                fma2(s, qp[4], k2.x); fma2(s, qp[5], k2.y);
                fma2(s, qp[6], k3.x); fma2(s, qp[7], k3.y);
                float sx, sy; upk2(s, sx, sy);
                float acc = sx + sy;
                acc += __shfl_xor_sync(0xffffffffu, acc, 1);
                acc += __shfl_xor_sync(0xffffffffu, acc, 2);
                acc += __shfl_xor_sync(0xffffffffu, acc, 4);
                p[jj] = acc;
            }
            if (need_mask) {
#pragma unroll
                for (int jj = 0; jj < 16; ++jj)
                    if (t0 + half * 16 + jj > lim_g) p[jj] = -1e30f;
            }

            float mt = m;
#pragma unroll
            for (int jj = 0; jj < 16; ++jj) mt = fmaxf(mt, p[jj]);
            const float alpha = __expf(m - mt);
            m = mt;
            float ls = 0.0f;
#pragma unroll
            for (int jj = 0; jj < 16; ++jj) { p[jj] = __expf(p[jj] - mt); ls += p[jj]; }
            l = l * alpha + ls;
            {
                ull al = pk2(alpha, alpha);
#pragma unroll
                for (int i = 0; i < 8; ++i) mul2(ov[i], al);
            }

#pragma unroll
            for (int jj = 0; jj < 16; ++jj) {
                const int j = half * 16 + jj;
                ull pj = pk2(p[jj], p[jj]);
                ulonglong2 v0 = *(const ulonglong2*)&Vs[j][c * 4];
                ulonglong2 v1 = *(const ulonglong2*)&Vs[j][32 + c * 4];
                ulonglong2 v2 = *(const ulonglong2*)&Vs[j][64 + c * 4];
                ulonglong2 v3 = *(const ulonglong2*)&Vs[j][96 + c * 4];
                fma2(ov[0], pj, v0.x); fma2(ov[1], pj, v0.y);
                fma2(ov[2], pj, v1.x); fma2(ov[3], pj, v1.y);
                fma2(ov[4], pj, v2.x); fma2(ov[5], pj, v2.y);
                fma2(ov[6], pj, v3.x); fma2(ov[7], pj, v3.y);
            }
        }
        __syncthreads();
    }

    const float inv = 1.0f / l;
    float* op = O + ((size_t)(b * L_ + qi) * H_ + h) * Dh_;
#pragma unroll
    for (int i = 0; i < 4; ++i) {
        float4 v;
        upk2(ov[2 * i],     v.x, v.y);
        upk2(ov[2 * i + 1], v.z, v.w);
        v.x *= inv; v.y *= inv; v.z *= inv; v.w *= inv;
        *(float4*)(op + i * 32 + c * 4) = v;
    }
}

// ---------------------------------------------------------------------------
extern "C" void kernel_launch(void* const* d_in, const int* in_sizes, int n_in,
                              void* d_out, int out_size) {
    const float* x  = (const float*)d_in[0];
    const float* ck = (const float*)d_in[1];
    const float* cv = (const float*)d_in[2];
    const float* Wq = (const float*)d_in[3];
    const float* Wk = (const float*)d_in[4];
    const float* Wv = (const float*)d_in[5];
    const float* Wo = (const float*)d_in[6];
    const float* qw = (const float*)d_in[7];
    const float* kw = (const float*)d_in[8];
    float* out = (float*)d_out;

    void *pq, *pk, *pv, *po, *pwh, *pwl, *pxh, *pxl, *poh, *pol;
    cudaGetSymbolAddress(&pq, g_q);
    cudaGetSymbolAddress(&pk, g_k);
    cudaGetSymbolAddress(&pv, g_v);
    cudaGetSymbolAddress(&po, g_o);
    cudaGetSymbolAddress(&pwh, g_whi);
    cudaGetSymbolAddress(&pwl, g_wlo);
    cudaGetSymbolAddress(&pxh, g_xhi);
    cudaGetSymbolAddress(&pxl, g_xlo);
    cudaGetSymbolAddress(&poh, g_ohi);
    cudaGetSymbolAddress(&pol, g_olo);
    float* Qb = (float*)pq;
    float* Kb = (float*)pk;
    float* Vb = (float*)pv;
    float* Ob = (float*)po;
    __nv_bfloat16* Whi = (__nv_bfloat16*)pwh;
    __nv_bfloat16* Wlo = (__nv_bfloat16*)pwl;
    __nv_bfloat16* Xhi = (__nv_bfloat16*)pxh;
    __nv_bfloat16* Xlo = (__nv_bfloat16*)pxl;
    __nv_bfloat16* Ohi = (__nv_bfloat16*)poh;
    __nv_bfloat16* Olo = (__nv_bfloat16*)pol;

    cudaFuncSetAttribute(gemm_mma, cudaFuncAttributeMaxDynamicSharedMemorySize, SMEMT);

    // pre-convert weights + x
    cvt_w<<<dim3(DD / 2048, 4), 256>>>(Wq, Wk, Wv, Wo, Whi, Wlo);
    cvt_x<<<(M_ * D_) / 2048, 256>>>(x, Xhi, Xlo);

    // QKV projection (tensor cores)
    gemm_mma<<<dim3(D_ / 128, M_ / 128, 3), 256, SMEMT>>>(Xhi, Xlo, Whi, Wlo, 0, Qb, Kb, Vb);

    rmsnorm_k<<<(M_ * H_) / 8, 256>>>(Qb, qw);
    rmsnorm_k<<<(M_ * H_) / 8, 256>>>(Kb, kw);

    attn_kernel<<<dim3(L_ / 32, H_, B_), 256>>>(Qb, Kb, Vb, ck, cv, Ob);

    // convert attention output, then output projection
    cvt_x<<<(M_ * D_) / 2048, 256>>>(Ob, Ohi, Olo);
    gemm_mma<<<dim3(D_ / 128, M_ / 128, 1), 256, SMEMT>>>(Ohi, Olo, Whi, Wlo, 3, out, out, out);
}

// round 7
// speedup vs baseline: 3.4970x; 1.0188x over previous
#include <cuda_runtime.h>
#include <cuda_bf16.h>
#include <cstdint>

// Problem constants
constexpr int B_  = 2;
constexpr int L_  = 256;
constexpr int D_  = 4096;
constexpr int H_  = 32;
constexpr int Dh_ = 128;
constexpr int S_  = 4224;
constexpr int SINK_ = 128;
constexpr int WINS_ = S_ - L_;     // 3968
constexpr int M_  = B_ * L_;       // 512
constexpr size_t DD = (size_t)D_ * D_;

// GEMM tiling
constexpr int BK = 32;
constexpr int NCHUNK = D_ / BK;        // 128
constexpr int A_ROW_B = 80;
constexpr int B_ROW_B = 272;
constexpr int A_TILE = 128 * A_ROW_B;  // 10240
constexpr int B_TILE = BK * B_ROW_B;   // 8704
constexpr int STAGE  = 2 * A_TILE + 2 * B_TILE;  // 37888
constexpr int SMEMT  = 2 * STAGE;      // 75776

// Attention smem: 2 stages x (K tile + V tile), each 32x128 fp32
constexpr int ATT_TILE = 32 * 128 * 4;          // 16384
constexpr int ATT_STAGE = 2 * ATT_TILE;         // 32768
constexpr int ATT_SMEM = 2 * ATT_STAGE;         // 65536

// scratch
__device__ float g_q[M_ * D_];
__device__ float g_k[M_ * D_];
__device__ float g_v[M_ * D_];
__device__ float g_o[M_ * D_];
__device__ __nv_bfloat16 g_whi[4 * DD];
__device__ __nv_bfloat16 g_wlo[4 * DD];
__device__ __nv_bfloat16 g_xhi[M_ * D_];
__device__ __nv_bfloat16 g_xlo[M_ * D_];
__device__ __nv_bfloat16 g_ohi[M_ * D_];
__device__ __nv_bfloat16 g_olo[M_ * D_];

typedef unsigned long long ull;

// ---- helpers ----
__device__ __forceinline__ uint32_t smem_u32(const void* p) {
    uint32_t a;
    asm("{ .reg .u64 t; cvta.to.shared.u64 t, %1; cvt.u32.u64 %0, t; }" : "=r"(a) : "l"(p));
    return a;
}
__device__ __forceinline__ void ldsm4(uint32_t* r, uint32_t a) {
    asm volatile("ldmatrix.sync.aligned.m8n8.x4.shared.b16 {%0,%1,%2,%3},[%4];"
                 : "=r"(r[0]), "=r"(r[1]), "=r"(r[2]), "=r"(r[3]) : "r"(a));
}
__device__ __forceinline__ void ldsm4t(uint32_t* r, uint32_t a) {
    asm volatile("ldmatrix.sync.aligned.m8n8.x4.trans.shared.b16 {%0,%1,%2,%3},[%4];"
                 : "=r"(r[0]), "=r"(r[1]), "=r"(r[2]), "=r"(r[3]) : "r"(a));
}
__device__ __forceinline__ void mma_bf(float* c, const uint32_t* a, uint32_t b0, uint32_t b1) {
    asm volatile(
        "mma.sync.aligned.m16n8k16.row.col.f32.bf16.bf16.f32 "
        "{%0,%1,%2,%3},{%4,%5,%6,%7},{%8,%9},{%0,%1,%2,%3};"
        : "+f"(c[0]), "+f"(c[1]), "+f"(c[2]), "+f"(c[3])
        : "r"(a[0]), "r"(a[1]), "r"(a[2]), "r"(a[3]), "r"(b0), "r"(b1));
}
__device__ __forceinline__ void split2(float x, float y, uint32_t& hi, uint32_t& lo) {
    __nv_bfloat16 hx = __float2bfloat16_rn(x);
    __nv_bfloat16 hy = __float2bfloat16_rn(y);
    __nv_bfloat16 lx = __float2bfloat16_rn(x - __bfloat162float(hx));
    __nv_bfloat16 ly = __float2bfloat16_rn(y - __bfloat162float(hy));
    hi = (uint32_t)__bfloat16_as_ushort(hx) | ((uint32_t)__bfloat16_as_ushort(hy) << 16);
    lo = (uint32_t)__bfloat16_as_ushort(lx) | ((uint32_t)__bfloat16_as_ushort(ly) << 16);
}
__device__ __forceinline__ void cpa16(uint32_t dst, const void* src) {
    asm volatile("cp.async.ca.shared.global [%0],[%1],16;" :: "r"(dst), "l"(src));
}
__device__ __forceinline__ void cpa_commit() {
    asm volatile("cp.async.commit_group;" ::: "memory");
}
__device__ __forceinline__ void cpa_wait1() {
    asm volatile("cp.async.wait_group 1;" ::: "memory");
}
__device__ __forceinline__ void cpa_wait0() {
    asm volatile("cp.async.wait_group 0;" ::: "memory");
}

// ---- packed f32x2 ----
__device__ __forceinline__ ull pk2(float x, float y) {
    ull r; asm("mov.b64 %0,{%1,%2};" : "=l"(r) : "f"(x), "f"(y)); return r;
}
__device__ __forceinline__ void upk2(ull v, float& x, float& y) {
    asm("mov.b64 {%0,%1},%2;" : "=f"(x), "=f"(y) : "l"(v));
}
__device__ __forceinline__ void fma2(ull& d, ull a, ull b) {
    asm("fma.rn.f32x2 %0,%1,%2,%0;" : "+l"(d) : "l"(a), "l"(b));
}
__device__ __forceinline__ void mul2(ull& d, ull a) {
    asm("mul.rn.f32x2 %0,%0,%1;" : "+l"(d) : "l"(a));
}

// ---------------------------------------------------------------------------
// Split-convert kernels: fp32 -> (hi, lo) bf16
// ---------------------------------------------------------------------------
__global__ __launch_bounds__(256) void cvt_w(
    const float* __restrict__ w0, const float* __restrict__ w1,
    const float* __restrict__ w2, const float* __restrict__ w3,
    __nv_bfloat16* __restrict__ hi, __nv_bfloat16* __restrict__ lo)
{
    const float* src = (blockIdx.y == 0) ? w0 : (blockIdx.y == 1) ? w1 : (blockIdx.y == 2) ? w2 : w3;
    const size_t base = (size_t)blockIdx.y * DD;
    const size_t i = ((size_t)blockIdx.x * 256 + threadIdx.x) * 8;
    float4 f0 = *(const float4*)(src + i);
    float4 f1 = *(const float4*)(src + i + 4);
    uint4 h, l;
    split2(f0.x, f0.y, h.x, l.x);
    split2(f0.z, f0.w, h.y, l.y);
    split2(f1.x, f1.y, h.z, l.z);
    split2(f1.z, f1.w, h.w, l.w);
    *(uint4*)(hi + base + i) = h;
    *(uint4*)(lo + base + i) = l;
}

__global__ __launch_bounds__(256) void cvt_x(
    const float* __restrict__ src,
    __nv_bfloat16* __restrict__ hi, __nv_bfloat16* __restrict__ lo)
{
    const size_t i = ((size_t)blockIdx.x * 256 + threadIdx.x) * 8;
    float4 f0 = *(const float4*)(src + i);
    float4 f1 = *(const float4*)(src + i + 4);
    uint4 h, l;
    split2(f0.x, f0.y, h.x, l.x);
    split2(f0.z, f0.w, h.y, l.y);
    split2(f1.x, f1.y, h.z, l.z);
    split2(f1.z, f1.w, h.w, l.w);
    *(uint4*)(hi + i) = h;
    *(uint4*)(lo + i) = l;
}

// ---------------------------------------------------------------------------
// mma.sync split-bf16 GEMM, 3 independent MMA passes, 2 CTAs/SM target.
// ---------------------------------------------------------------------------
__global__ __launch_bounds__(256, 2) void gemm_mma(
    const __nv_bfloat16* __restrict__ Ahi, const __nv_bfloat16* __restrict__ Alo,
    const __nv_bfloat16* __restrict__ Whi, const __nv_bfloat16* __restrict__ Wlo,
    int wzoff,
    float* __restrict__ C0, float* __restrict__ C1, float* __restrict__ C2)
{
    float* C = (blockIdx.z == 0) ? C0 : (blockIdx.z == 1) ? C1 : C2;
    const size_t woff = (size_t)(blockIdx.z + wzoff) * DD;

    extern __shared__ char smem[];
    const uint32_t sb = smem_u32(smem);
    const int tid  = threadIdx.x;
    const int wid  = tid >> 5;
    const int lane = tid & 31;
    const int wm   = wid & 1;
    const int wn   = wid >> 1;

    const int m0 = blockIdx.y * 128;
    const int n0 = blockIdx.x * 128;

    const __nv_bfloat16* AhiB = Ahi + (size_t)m0 * D_;
    const __nv_bfloat16* AloB = Alo + (size_t)m0 * D_;
    const __nv_bfloat16* WhiB = Whi + woff + n0;
    const __nv_bfloat16* WloB = Wlo + woff + n0;

    float acc[4][4][4];
#pragma unroll
    for (int mt = 0; mt < 4; ++mt)
#pragma unroll
        for (int nt = 0; nt < 4; ++nt)
#pragma unroll
            for (int e = 0; e < 4; ++e) acc[mt][nt][e] = 0.0f;

    const int a_r   = (lane & 7) + ((lane >> 3) & 1) * 8;
    const int a_kb  = (lane >> 4) * 16;
    const int b_kr  = (lane & 7) + (lane >> 4) * 8;
    const int b_nb  = ((lane >> 3) & 1) * 16;

    auto issue_stage = [&](int ch, int s) {
        const uint32_t stA = sb + s * STAGE;
        const uint32_t stB = stA + 2 * A_TILE;
#pragma unroll
        for (int i = 0; i < 2; ++i) {
            const int c = tid * 2 + i;
            const int ar = c >> 2, akc = c & 3;
            const size_t aoff = (size_t)ar * D_ + ch * BK + akc * 8;
            const uint32_t adst = stA + ar * A_ROW_B + akc * 16;
            cpa16(adst, AhiB + aoff);
            cpa16(adst + A_TILE, AloB + aoff);
            const int br = c >> 4, bnc = c & 15;
            const size_t boff = (size_t)(ch * BK + br) * D_ + bnc * 8;
            const uint32_t bdst = stB + br * B_ROW_B + bnc * 16;
            cpa16(bdst, WhiB + boff);
            cpa16(bdst + B_TILE, WloB + boff);
        }
        cpa_commit();
    };

    issue_stage(0, 0);

    for (int ch = 0; ch < NCHUNK; ++ch) {
        const int s = ch & 1;
        if (ch + 1 < NCHUNK) { issue_stage(ch + 1, s ^ 1); cpa_wait1(); }
        else cpa_wait0();
        __syncthreads();

        const uint32_t Ah = sb + s * STAGE;
        const uint32_t Al = Ah + A_TILE;
        const uint32_t Bh = Ah + 2 * A_TILE;
        const uint32_t Bl = Bh + B_TILE;

#pragma unroll
        for (int kc = 0; kc < 2; ++kc) {
            uint32_t ah[4][4], al[4][4];
            uint32_t bh[4][2], bl[4][2];
            const uint32_t a_addr = (uint32_t)((wm * 64 + a_r) * A_ROW_B + kc * 32 + a_kb);
#pragma unroll
            for (int mt = 0; mt < 4; ++mt) {
                ldsm4(ah[mt], Ah + a_addr + mt * 16 * A_ROW_B);
                ldsm4(al[mt], Al + a_addr + mt * 16 * A_ROW_B);
            }
            const uint32_t b_addr = (uint32_t)((kc * 16 + b_kr) * B_ROW_B + (wn * 32) * 2 + b_nb);
#pragma unroll
            for (int p = 0; p < 2; ++p) {
                uint32_t rh[4], rl[4];
                ldsm4t(rh, Bh + b_addr + p * 32);
                ldsm4t(rl, Bl + b_addr + p * 32);
                bh[2 * p][0] = rh[0]; bh[2 * p][1] = rh[2];
                bh[2 * p + 1][0] = rh[1]; bh[2 * p + 1][1] = rh[3];
                bl[2 * p][0] = rl[0]; bl[2 * p][1] = rl[2];
                bl[2 * p + 1][0] = rl[1]; bl[2 * p + 1][1] = rl[3];
            }
            // 3 independent passes: same-acc reuse distance = 16 MMAs
#pragma unroll
            for (int mt = 0; mt < 4; ++mt)
#pragma unroll
                for (int nt = 0; nt < 4; ++nt)
                    mma_bf(acc[mt][nt], ah[mt], bh[nt][0], bh[nt][1]);
#pragma unroll
            for (int mt = 0; mt < 4; ++mt)
#pragma unroll
                for (int nt = 0; nt < 4; ++nt)
                    mma_bf(acc[mt][nt], ah[mt], bl[nt][0], bl[nt][1]);
#pragma unroll
            for (int mt = 0; mt < 4; ++mt)
#pragma unroll
                for (int nt = 0; nt < 4; ++nt)
                    mma_bf(acc[mt][nt], al[mt], bh[nt][0], bh[nt][1]);
        }
        __syncthreads();
    }

    const int gr = lane >> 2;
    const int gc = lane & 3;
#pragma unroll
    for (int mt = 0; mt < 4; ++mt) {
        const int row = m0 + wm * 64 + mt * 16 + gr;
        float* c0 = C + (size_t)row * D_ + n0 + wn * 32;
        float* c1 = C + (size_t)(row + 8) * D_ + n0 + wn * 32;
#pragma unroll
        for (int nt = 0; nt < 4; ++nt) {
            *(float2*)(c0 + nt * 8 + gc * 2) = make_float2(acc[mt][nt][0], acc[mt][nt][1]);
            *(float2*)(c1 + nt * 8 + gc * 2) = make_float2(acc[mt][nt][2], acc[mt][nt][3]);
        }
    }
}

// ---------------------------------------------------------------------------
__global__ __launch_bounds__(256) void rmsnorm_k(float* __restrict__ X,
                                                 const float* __restrict__ w) {
    const int row  = (blockIdx.x * 256 + threadIdx.x) >> 5;
    const int lane = threadIdx.x & 31;
    float* p = X + (size_t)row * 128 + lane * 4;
    float4 v = *(float4*)p;
    float ss = v.x * v.x + v.y * v.y + v.z * v.z + v.w * v.w;
#pragma unroll
    for (int o = 16; o; o >>= 1) ss += __shfl_xor_sync(0xffffffffu, ss, o);
    float r = rsqrtf(ss * (1.0f / 128.0f) + 1e-6f);
    float4 wv = *(const float4*)(w + lane * 4);
    v.x *= r * wv.x; v.y *= r * wv.y; v.z *= r * wv.z; v.w *= r * wv.w;
    *(float4*)p = v;
}

// ---------------------------------------------------------------------------
// Flash attention: FFMA2, cp.async double-buffered K/V tiles, 2 CTAs/SM.
// ---------------------------------------------------------------------------
__global__ __launch_bounds__(256, 2) void attn_kernel(const float* __restrict__ Q,
                                                      const float* __restrict__ Kn,
                                                      const float* __restrict__ Vn,
                                                      const float* __restrict__ cK,
                                                      const float* __restrict__ cV,
                                                      float* __restrict__ O) {
    extern __shared__ char asmem[];
    const uint32_t sb = smem_u32(asmem);

    const int tid = threadIdx.x;
    const int r   = tid >> 3;
    const int c   = tid & 7;
    const int h   = blockIdx.y;
    const int b   = blockIdx.z;
    const int q0  = blockIdx.x * 32;
    const int qi  = q0 + r;
    const int lim_g = WINS_ + qi;

    const float scale = 0.08838834764831845f;

    ull qp[8];
    {
        const float* qptr = Q + ((size_t)(b * L_ + qi) * H_ + h) * Dh_;
#pragma unroll
        for (int i = 0; i < 4; ++i) {
            float4 v = *(const float4*)(qptr + i * 32 + c * 4);
            qp[2 * i]     = pk2(v.x * scale, v.y * scale);
            qp[2 * i + 1] = pk2(v.z * scale, v.w * scale);
        }
    }

    ull ov[8];
#pragma unroll
    for (int i = 0; i < 8; ++i) ov[i] = 0ull;
    float m = -1e30f, l = 0.0f;

    const int t_end = min(S_, WINS_ + q0 + 32);
    const int n_it  = (t_end + 31) / 32;

    // per-thread load row/cols: row r, dims i*32 + c*4
    auto issue_tile = [&](int it, int s) {
        const int sg = it * 32 + r;
        const float *ksrc, *vsrc;
        if (sg < WINS_) {
            const int src = (sg < SINK_) ? sg : sg + L_;
            const size_t off = (((size_t)b * S_ + src) * H_ + h) * Dh_;
            ksrc = cK + off; vsrc = cV + off;
        } else {
            const size_t off = (((size_t)b * L_ + (sg - WINS_)) * H_ + h) * Dh_;
            ksrc = Kn + off; vsrc = Vn + off;
        }
        const uint32_t kbase = sb + s * ATT_STAGE + r * 512;
        const uint32_t vbase = kbase + ATT_TILE;
#pragma unroll
        for (int i = 0; i < 4; ++i) {
            const int d = i * 32 + c * 4;
            cpa16(kbase + d * 4, ksrc + d);
            cpa16(vbase + d * 4, vsrc + d);
        }
        cpa_commit();
    };

    issue_tile(0, 0);

    for (int it = 0; it < n_it; ++it) {
        const int s = it & 1;
        const int t0 = it * 32;
        if (it + 1 < n_it) { issue_tile(it + 1, s ^ 1); cpa_wait1(); }
        else cpa_wait0();
        __syncthreads();

        const float* Ks = (const float*)(asmem + s * ATT_STAGE);
        const float* Vs = (const float*)(asmem + s * ATT_STAGE + ATT_TILE);

        const bool need_mask = (t0 + 31 > lim_g);

#pragma unroll
        for (int half = 0; half < 2; ++half) {
            float p[16];
#pragma unroll
            for (int jj = 0; jj < 16; ++jj) {
                const int j = half * 16 + jj;
                const float* kr = Ks + j * 128;
                ulonglong2 k0 = *(const ulonglong2*)(kr + c * 4);
                ulonglong2 k1 = *(const ulonglong2*)(kr + 32 + c * 4);
                ulonglong2 k2 = *(const ulonglong2*)(kr + 64 + c * 4);
                ulonglong2 k3 = *(const ulonglong2*)(kr + 96 + c * 4);
                ull sacc = 0ull;
                fma2(sacc, qp[0], k0.x); fma2(sacc, qp[1], k0.y);
                fma2(sacc, qp[2], k1.x); fma2(sacc, qp[3], k1.y);
                fma2(sacc, qp[4], k2.x); fma2(sacc, qp[5], k2.y);
                fma2(sacc, qp[6], k3.x); fma2(sacc, qp[7], k3.y);
                float sx, sy; upk2(sacc, sx, sy);
                float acc = sx + sy;
                acc += __shfl_xor_sync(0xffffffffu, acc, 1);
                acc += __shfl_xor_sync(0xffffffffu, acc, 2);
                acc += __shfl_xor_sync(0xffffffffu, acc, 4);
                p[jj] = acc;
            }
            if (need_mask) {
#pragma unroll
                for (int jj = 0; jj < 16; ++jj)
                    if (t0 + half * 16 + jj > lim_g) p[jj] = -1e30f;
            }

            float mt = m;
#pragma unroll
            for (int jj = 0; jj < 16; ++jj) mt = fmaxf(mt, p[jj]);
            const float alpha = __expf(m - mt);
            m = mt;
            float ls = 0.0f;
#pragma unroll
            for (int jj = 0; jj < 16; ++jj) { p[jj] = __expf(p[jj] - mt); ls += p[jj]; }
            l = l * alpha + ls;
            {
                ull al = pk2(alpha, alpha);
#pragma unroll
                for (int i = 0; i < 8; ++i) mul2(ov[i], al);
            }

#pragma unroll
            for (int jj = 0; jj < 16; ++jj) {
                const int j = half * 16 + jj;
                const float* vr = Vs + j * 128;
                ull pj = pk2(p[jj], p[jj]);
                ulonglong2 v0 = *(const ulonglong2*)(vr + c * 4);
                ulonglong2 v1 = *(const ulonglong2*)(vr + 32 + c * 4);
                ulonglong2 v2 = *(const ulonglong2*)(vr + 64 + c * 4);
                ulonglong2 v3 = *(const ulonglong2*)(vr + 96 + c * 4);
                fma2(ov[0], pj, v0.x); fma2(ov[1], pj, v0.y);
                fma2(ov[2], pj, v1.x); fma2(ov[3], pj, v1.y);
                fma2(ov[4], pj, v2.x); fma2(ov[5], pj, v2.y);
                fma2(ov[6], pj, v3.x); fma2(ov[7], pj, v3.y);
            }
        }
        __syncthreads();
    }

    const float inv = 1.0f / l;
    float* op = O + ((size_t)(b * L_ + qi) * H_ + h) * Dh_;
#pragma unroll
    for (int i = 0; i < 4; ++i) {
        float4 v;
        upk2(ov[2 * i],     v.x, v.y);
        upk2(ov[2 * i + 1], v.z, v.w);
        v.x *= inv; v.y *= inv; v.z *= inv; v.w *= inv;
        *(float4*)(op + i * 32 + c * 4) = v;
    }
}

// ---------------------------------------------------------------------------
extern "C" void kernel_launch(void* const* d_in, const int* in_sizes, int n_in,
                              void* d_out, int out_size) {
    const float* x  = (const float*)d_in[0];
    const float* ck = (const float*)d_in[1];
    const float* cv = (const float*)d_in[2];
    const float* Wq = (const float*)d_in[3];
    const float* Wk = (const float*)d_in[4];
    const float* Wv = (const float*)d_in[5];
    const float* Wo = (const float*)d_in[6];
    const float* qw = (const float*)d_in[7];
    const float* kw = (const float*)d_in[8];
    float* out = (float*)d_out;

    void *pq, *pk, *pv, *po, *pwh, *pwl, *pxh, *pxl, *poh, *pol;
    cudaGetSymbolAddress(&pq, g_q);
    cudaGetSymbolAddress(&pk, g_k);
    cudaGetSymbolAddress(&pv, g_v);
    cudaGetSymbolAddress(&po, g_o);
    cudaGetSymbolAddress(&pwh, g_whi);
    cudaGetSymbolAddress(&pwl, g_wlo);
    cudaGetSymbolAddress(&pxh, g_xhi);
    cudaGetSymbolAddress(&pxl, g_xlo);
    cudaGetSymbolAddress(&poh, g_ohi);
    cudaGetSymbolAddress(&pol, g_olo);
    float* Qb = (float*)pq;
    float* Kb = (float*)pk;
    float* Vb = (float*)pv;
    float* Ob = (float*)po;
    __nv_bfloat16* Whi = (__nv_bfloat16*)pwh;
    __nv_bfloat16* Wlo = (__nv_bfloat16*)pwl;
    __nv_bfloat16* Xhi = (__nv_bfloat16*)pxh;
    __nv_bfloat16* Xlo = (__nv_bfloat16*)pxl;
    __nv_bfloat16* Ohi = (__nv_bfloat16*)poh;
    __nv_bfloat16* Olo = (__nv_bfloat16*)pol;

    cudaFuncSetAttribute(gemm_mma, cudaFuncAttributeMaxDynamicSharedMemorySize, SMEMT);
    cudaFuncSetAttribute(attn_kernel, cudaFuncAttributeMaxDynamicSharedMemorySize, ATT_SMEM);

    cvt_w<<<dim3(DD / 2048, 4), 256>>>(Wq, Wk, Wv, Wo, Whi, Wlo);
    cvt_x<<<(M_ * D_) / 2048, 256>>>(x, Xhi, Xlo);

    gemm_mma<<<dim3(D_ / 128, M_ / 128, 3), 256, SMEMT>>>(Xhi, Xlo, Whi, Wlo, 0, Qb, Kb, Vb);

    rmsnorm_k<<<(M_ * H_) / 8, 256>>>(Qb, qw);
    rmsnorm_k<<<(M_ * H_) / 8, 256>>>(Kb, kw);

    attn_kernel<<<dim3(L_ / 32, H_, B_), 256, ATT_SMEM>>>(Qb, Kb, Vb, ck, cv, Ob);

    cvt_x<<<(M_ * D_) / 2048, 256>>>(Ob, Ohi, Olo);
    gemm_mma<<<dim3(D_ / 128, M_ / 128, 1), 256, SMEMT>>>(Ohi, Olo, Whi, Wlo, 3, out, out, out);
}

// round 8
// speedup vs baseline: 6.9188x; 1.9785x over previous
#include <cuda_runtime.h>
#include <cuda_bf16.h>
#include <cstdint>

// Problem constants
constexpr int B_  = 2;
constexpr int L_  = 256;
constexpr int D_  = 4096;
constexpr int H_  = 32;
constexpr int Dh_ = 128;
constexpr int S_  = 4224;
constexpr int SINK_ = 128;
constexpr int WINS_ = S_ - L_;     // 3968
constexpr int M_  = B_ * L_;       // 512
constexpr size_t DD = (size_t)D_ * D_;
constexpr size_t CACHE_E = (size_t)B_ * S_ * H_ * Dh_;  // 34,603,008

// GEMM tiling
constexpr int BK = 32;
constexpr int NCHUNK = D_ / BK;        // 128
constexpr int A_ROW_B = 80;
constexpr int B_ROW_B = 272;
constexpr int A_TILE = 128 * A_ROW_B;  // 10240
constexpr int B_TILE = BK * B_ROW_B;   // 8704
constexpr int STAGE  = 2 * A_TILE + 2 * B_TILE;  // 37888
constexpr int SMEMT  = 2 * STAGE;      // 75776

// Attention smem layout (bytes)
constexpr int ARB = 272;                       // padded row (128 bf16 -> 272B)
constexpr int AQ_COMP = 32 * ARB;              // 8704 (Q hi or lo)
constexpr int AT_COMP = 64 * ARB;              // 17408 (K/V tile component)
constexpr int AT_STG  = 4 * AT_COMP;           // 69632 (Khi,Klo,Vhi,Vlo)
constexpr int ATT_SMEM = 2 * AQ_COMP + 2 * AT_STG;  // 156672

// scratch
__device__ float g_q[M_ * D_];
__device__ float g_k[M_ * D_];
__device__ float g_v[M_ * D_];
__device__ float g_o[M_ * D_];
__device__ __nv_bfloat16 g_whi[4 * DD];
__device__ __nv_bfloat16 g_wlo[4 * DD];
__device__ __nv_bfloat16 g_xhi[M_ * D_];
__device__ __nv_bfloat16 g_xlo[M_ * D_];
__device__ __nv_bfloat16 g_ohi[M_ * D_];
__device__ __nv_bfloat16 g_olo[M_ * D_];
// split cache + new K/V
__device__ __nv_bfloat16 g_ckhi[CACHE_E];
__device__ __nv_bfloat16 g_cklo[CACHE_E];
__device__ __nv_bfloat16 g_cvhi[CACHE_E];
__device__ __nv_bfloat16 g_cvlo[CACHE_E];
__device__ __nv_bfloat16 g_nkhi[M_ * D_];
__device__ __nv_bfloat16 g_nklo[M_ * D_];
__device__ __nv_bfloat16 g_nvhi[M_ * D_];
__device__ __nv_bfloat16 g_nvlo[M_ * D_];

// ---- helpers ----
__device__ __forceinline__ uint32_t smem_u32(const void* p) {
    uint32_t a;
    asm("{ .reg .u64 t; cvta.to.shared.u64 t, %1; cvt.u32.u64 %0, t; }" : "=r"(a) : "l"(p));
    return a;
}
__device__ __forceinline__ void ldsm4(uint32_t* r, uint32_t a) {
    asm volatile("ldmatrix.sync.aligned.m8n8.x4.shared.b16 {%0,%1,%2,%3},[%4];"
                 : "=r"(r[0]), "=r"(r[1]), "=r"(r[2]), "=r"(r[3]) : "r"(a));
}
__device__ __forceinline__ void ldsm4t(uint32_t* r, uint32_t a) {
    asm volatile("ldmatrix.sync.aligned.m8n8.x4.trans.shared.b16 {%0,%1,%2,%3},[%4];"
                 : "=r"(r[0]), "=r"(r[1]), "=r"(r[2]), "=r"(r[3]) : "r"(a));
}
__device__ __forceinline__ void mma_bf(float* c, const uint32_t* a, uint32_t b0, uint32_t b1) {
    asm volatile(
        "mma.sync.aligned.m16n8k16.row.col.f32.bf16.bf16.f32 "
        "{%0,%1,%2,%3},{%4,%5,%6,%7},{%8,%9},{%0,%1,%2,%3};"
        : "+f"(c[0]), "+f"(c[1]), "+f"(c[2]), "+f"(c[3])
        : "r"(a[0]), "r"(a[1]), "r"(a[2]), "r"(a[3]), "r"(b0), "r"(b1));
}
__device__ __forceinline__ void split2(float x, float y, uint32_t& hi, uint32_t& lo) {
    __nv_bfloat16 hx = __float2bfloat16_rn(x);
    __nv_bfloat16 hy = __float2bfloat16_rn(y);
    __nv_bfloat16 lx = __float2bfloat16_rn(x - __bfloat162float(hx));
    __nv_bfloat16 ly = __float2bfloat16_rn(y - __bfloat162float(hy));
    hi = (uint32_t)__bfloat16_as_ushort(hx) | ((uint32_t)__bfloat16_as_ushort(hy) << 16);
    lo = (uint32_t)__bfloat16_as_ushort(lx) | ((uint32_t)__bfloat16_as_ushort(ly) << 16);
}
__device__ __forceinline__ void cpa16(uint32_t dst, const void* src) {
    asm volatile("cp.async.ca.shared.global [%0],[%1],16;" :: "r"(dst), "l"(src));
}
__device__ __forceinline__ void cpa_commit() {
    asm volatile("cp.async.commit_group;" ::: "memory");
}
__device__ __forceinline__ void cpa_wait1() {
    asm volatile("cp.async.wait_group 1;" ::: "memory");
}
__device__ __forceinline__ void cpa_wait0() {
    asm volatile("cp.async.wait_group 0;" ::: "memory");
}

// ---------------------------------------------------------------------------
// Split-convert kernels: fp32 -> (hi, lo) bf16. 8 elems/thread.
// ---------------------------------------------------------------------------
__global__ __launch_bounds__(256) void cvt_w(
    const float* __restrict__ w0, const float* __restrict__ w1,
    const float* __restrict__ w2, const float* __restrict__ w3,
    __nv_bfloat16* __restrict__ hi, __nv_bfloat16* __restrict__ lo)
{
    const float* src = (blockIdx.y == 0) ? w0 : (blockIdx.y == 1) ? w1 : (blockIdx.y == 2) ? w2 : w3;
    const size_t base = (size_t)blockIdx.y * DD;
    const size_t i = ((size_t)blockIdx.x * 256 + threadIdx.x) * 8;
    float4 f0 = *(const float4*)(src + i);
    float4 f1 = *(const float4*)(src + i + 4);
    uint4 h, l;
    split2(f0.x, f0.y, h.x, l.x);
    split2(f0.z, f0.w, h.y, l.y);
    split2(f1.x, f1.y, h.z, l.z);
    split2(f1.z, f1.w, h.w, l.w);
    *(uint4*)(hi + base + i) = h;
    *(uint4*)(lo + base + i) = l;
}

__global__ __launch_bounds__(256) void cvt_x(
    const float* __restrict__ src,
    __nv_bfloat16* __restrict__ hi, __nv_bfloat16* __restrict__ lo)
{
    const size_t i = ((size_t)blockIdx.x * 256 + threadIdx.x) * 8;
    float4 f0 = *(const float4*)(src + i);
    float4 f1 = *(const float4*)(src + i + 4);
    uint4 h, l;
    split2(f0.x, f0.y, h.x, l.x);
    split2(f0.z, f0.w, h.y, l.y);
    split2(f1.x, f1.y, h.z, l.z);
    split2(f1.z, f1.w, h.w, l.w);
    *(uint4*)(hi + i) = h;
    *(uint4*)(lo + i) = l;
}

// ---------------------------------------------------------------------------
// mma.sync split-bf16 GEMM (unchanged from round 7)
// ---------------------------------------------------------------------------
__global__ __launch_bounds__(256, 2) void gemm_mma(
    const __nv_bfloat16* __restrict__ Ahi, const __nv_bfloat16* __restrict__ Alo,
    const __nv_bfloat16* __restrict__ Whi, const __nv_bfloat16* __restrict__ Wlo,
    int wzoff,
    float* __restrict__ C0, float* __restrict__ C1, float* __restrict__ C2)
{
    float* C = (blockIdx.z == 0) ? C0 : (blockIdx.z == 1) ? C1 : C2;
    const size_t woff = (size_t)(blockIdx.z + wzoff) * DD;

    extern __shared__ char smem[];
    const uint32_t sb = smem_u32(smem);
    const int tid  = threadIdx.x;
    const int wid  = tid >> 5;
    const int lane = tid & 31;
    const int wm   = wid & 1;
    const int wn   = wid >> 1;

    const int m0 = blockIdx.y * 128;
    const int n0 = blockIdx.x * 128;

    const __nv_bfloat16* AhiB = Ahi + (size_t)m0 * D_;
    const __nv_bfloat16* AloB = Alo + (size_t)m0 * D_;
    const __nv_bfloat16* WhiB = Whi + woff + n0;
    const __nv_bfloat16* WloB = Wlo + woff + n0;

    float acc[4][4][4];
#pragma unroll
    for (int mt = 0; mt < 4; ++mt)
#pragma unroll
        for (int nt = 0; nt < 4; ++nt)
#pragma unroll
            for (int e = 0; e < 4; ++e) acc[mt][nt][e] = 0.0f;

    const int a_r   = (lane & 7) + ((lane >> 3) & 1) * 8;
    const int a_kb  = (lane >> 4) * 16;
    const int b_kr  = (lane & 7) + (lane >> 4) * 8;
    const int b_nb  = ((lane >> 3) & 1) * 16;

    auto issue_stage = [&](int ch, int s) {
        const uint32_t stA = sb + s * STAGE;
        const uint32_t stB = stA + 2 * A_TILE;
#pragma unroll
        for (int i = 0; i < 2; ++i) {
            const int c = tid * 2 + i;
            const int ar = c >> 2, akc = c & 3;
            const size_t aoff = (size_t)ar * D_ + ch * BK + akc * 8;
            const uint32_t adst = stA + ar * A_ROW_B + akc * 16;
            cpa16(adst, AhiB + aoff);
            cpa16(adst + A_TILE, AloB + aoff);
            const int br = c >> 4, bnc = c & 15;
            const size_t boff = (size_t)(ch * BK + br) * D_ + bnc * 8;
            const uint32_t bdst = stB + br * B_ROW_B + bnc * 16;
            cpa16(bdst, WhiB + boff);
            cpa16(bdst + B_TILE, WloB + boff);
        }
        cpa_commit();
    };

    issue_stage(0, 0);

    for (int ch = 0; ch < NCHUNK; ++ch) {
        const int s = ch & 1;
        if (ch + 1 < NCHUNK) { issue_stage(ch + 1, s ^ 1); cpa_wait1(); }
        else cpa_wait0();
        __syncthreads();

        const uint32_t Ah = sb + s * STAGE;
        const uint32_t Al = Ah + A_TILE;
        const uint32_t Bh = Ah + 2 * A_TILE;
        const uint32_t Bl = Bh + B_TILE;

#pragma unroll
        for (int kc = 0; kc < 2; ++kc) {
            uint32_t ah[4][4], al[4][4];
            uint32_t bh[4][2], bl[4][2];
            const uint32_t a_addr = (uint32_t)((wm * 64 + a_r) * A_ROW_B + kc * 32 + a_kb);
#pragma unroll
            for (int mt = 0; mt < 4; ++mt) {
                ldsm4(ah[mt], Ah + a_addr + mt * 16 * A_ROW_B);
                ldsm4(al[mt], Al + a_addr + mt * 16 * A_ROW_B);
            }
            const uint32_t b_addr = (uint32_t)((kc * 16 + b_kr) * B_ROW_B + (wn * 32) * 2 + b_nb);
#pragma unroll
            for (int p = 0; p < 2; ++p) {
                uint32_t rh[4], rl[4];
                ldsm4t(rh, Bh + b_addr + p * 32);
                ldsm4t(rl, Bl + b_addr + p * 32);
                bh[2 * p][0] = rh[0]; bh[2 * p][1] = rh[2];
                bh[2 * p + 1][0] = rh[1]; bh[2 * p + 1][1] = rh[3];
                bl[2 * p][0] = rl[0]; bl[2 * p][1] = rl[2];
                bl[2 * p + 1][0] = rl[1]; bl[2 * p + 1][1] = rl[3];
            }
#pragma unroll
            for (int mt = 0; mt < 4; ++mt)
#pragma unroll
                for (int nt = 0; nt < 4; ++nt)
                    mma_bf(acc[mt][nt], ah[mt], bh[nt][0], bh[nt][1]);
#pragma unroll
            for (int mt = 0; mt < 4; ++mt)
#pragma unroll
                for (int nt = 0; nt < 4; ++nt)
                    mma_bf(acc[mt][nt], ah[mt], bl[nt][0], bl[nt][1]);
#pragma unroll
            for (int mt = 0; mt < 4; ++mt)
#pragma unroll
                for (int nt = 0; nt < 4; ++nt)
                    mma_bf(acc[mt][nt], al[mt], bh[nt][0], bh[nt][1]);
        }
        __syncthreads();
    }

    const int gr = lane >> 2;
    const int gc = lane & 3;
#pragma unroll
    for (int mt = 0; mt < 4; ++mt) {
        const int row = m0 + wm * 64 + mt * 16 + gr;
        float* c0 = C + (size_t)row * D_ + n0 + wn * 32;
        float* c1 = C + (size_t)(row + 8) * D_ + n0 + wn * 32;
#pragma unroll
        for (int nt = 0; nt < 4; ++nt) {
            *(float2*)(c0 + nt * 8 + gc * 2) = make_float2(acc[mt][nt][0], acc[mt][nt][1]);
            *(float2*)(c1 + nt * 8 + gc * 2) = make_float2(acc[mt][nt][2], acc[mt][nt][3]);
        }
    }
}

// ---------------------------------------------------------------------------
__global__ __launch_bounds__(256) void rmsnorm_k(float* __restrict__ X,
                                                 const float* __restrict__ w) {
    const int row  = (blockIdx.x * 256 + threadIdx.x) >> 5;
    const int lane = threadIdx.x & 31;
    float* p = X + (size_t)row * 128 + lane * 4;
    float4 v = *(float4*)p;
    float ss = v.x * v.x + v.y * v.y + v.z * v.z + v.w * v.w;
#pragma unroll
    for (int o = 16; o; o >>= 1) ss += __shfl_xor_sync(0xffffffffu, ss, o);
    float r = rsqrtf(ss * (1.0f / 128.0f) + 1e-6f);
    float4 wv = *(const float4*)(w + lane * 4);
    v.x *= r * wv.x; v.y *= r * wv.y; v.z *= r * wv.z; v.w *= r * wv.w;
    *(float4*)p = v;
}

// ---------------------------------------------------------------------------
// MMA flash attention. CTA = 32 queries (one head). 8 warps = 2 q-halves(mg)
// x 4 key-window splits(sp). 64-key tiles; warp sp owns keys [sp*16, sp*16+16)
// of each tile. Split-bf16 (3 MMAs) for QK and PV. Per-warp online softmax,
// 4-way merge at end.
// ---------------------------------------------------------------------------
__global__ __launch_bounds__(256) void attn_mma(
    const float* __restrict__ Qf,
    const __nv_bfloat16* __restrict__ CKhi, const __nv_bfloat16* __restrict__ CKlo,
    const __nv_bfloat16* __restrict__ CVhi, const __nv_bfloat16* __restrict__ CVlo,
    const __nv_bfloat16* __restrict__ NKhi, const __nv_bfloat16* __restrict__ NKlo,
    const __nv_bfloat16* __restrict__ NVhi, const __nv_bfloat16* __restrict__ NVlo,
    float* __restrict__ O)
{
    extern __shared__ char asmem[];
    const uint32_t sb = smem_u32(asmem);

    const int tid  = threadIdx.x;
    const int wid  = tid >> 5;
    const int lane = tid & 31;
    const int mg   = wid & 1;         // q half (0: q0..15, 1: q16..31)
    const int sp   = wid >> 1;        // key-window split 0..3
    const int h    = blockIdx.y;
    const int b    = blockIdx.z;
    const int q0   = blockIdx.x * 32;

    const float scale = 0.08838834764831845f;  // 1/sqrt(128)

    // smem offsets
    const uint32_t Qhi_o = sb;
    const uint32_t Qlo_o = sb + AQ_COMP;
    const uint32_t STG0  = sb + 2 * AQ_COMP;

    // ---- fill Q tiles (pre-scaled, split) ----
    {
        const int row = tid >> 3;
        const int d0  = (tid & 7) * 16;
        const float* qp = Qf + ((size_t)(b * L_ + q0 + row) * H_ + h) * Dh_ + d0;
        const uint32_t dst = (uint32_t)(row * ARB + d0 * 2);
#pragma unroll
        for (int i = 0; i < 8; ++i) {
            float2 f = *(const float2*)(qp + 2 * i);
            uint32_t hreg, lreg;
            split2(f.x * scale, f.y * scale, hreg, lreg);
            *(uint32_t*)(asmem + dst + 4 * i) = hreg;
            *(uint32_t*)(asmem + AQ_COMP + dst + 4 * i) = lreg;
        }
    }
    __syncthreads();

    // ldmatrix lane addressing (byte units) — identical recipe to gemm_mma
    const int a_r  = (lane & 7) + ((lane >> 3) & 1) * 8;
    const int a_kb = (lane >> 4) * 16;
    const int b_kr = (lane & 7) + (lane >> 4) * 8;
    const int b_nb = ((lane >> 3) & 1) * 16;

    // ---- Q fragments resident (A operand, 8 ksteps, hi+lo) ----
    uint32_t qh[8][4], ql[8][4];
#pragma unroll
    for (int ks = 0; ks < 8; ++ks) {
        const uint32_t qa = (uint32_t)((mg * 16 + a_r) * ARB + ks * 32 + a_kb);
        ldsm4(qh[ks], Qhi_o + qa);
        ldsm4(ql[ks], Qlo_o + qa);
    }

    // state
    float o[16][4];
#pragma unroll
    for (int nt = 0; nt < 16; ++nt)
#pragma unroll
        for (int e = 0; e < 4; ++e) o[nt][e] = 0.0f;
    float m0 = -1e30f, m1 = -1e30f, l0 = 0.0f, l1 = 0.0f;

    const int t_end = WINS_ + q0 + 32;
    const int n_t   = (t_end + 63) / 64;
    const int wlim  = WINS_ + q0 + mg * 16;   // warp-uniform strictest row limit
    const int lim0  = wlim + (lane >> 2);
    const int lim1  = lim0 + 8;

    // tile loader: 64 rows x 128 d x 4 components, 16 cpa16 per thread
    auto issue_tile = [&](int t, int s) {
        const int sg = t * 64 + (tid >> 2);
        const __nv_bfloat16 *kh, *kl, *vh, *vl;
        if (sg < WINS_) {
            const int src = (sg < SINK_) ? sg : sg + L_;
            const size_t off = (((size_t)b * S_ + src) * H_ + h) * Dh_;
            kh = CKhi + off; kl = CKlo + off; vh = CVhi + off; vl = CVlo + off;
        } else {
            const size_t off = (((size_t)b * L_ + (sg - WINS_)) * H_ + h) * Dh_;
            kh = NKhi + off; kl = NKlo + off; vh = NVhi + off; vl = NVlo + off;
        }
        const uint32_t base = STG0 + s * AT_STG + (tid >> 2) * ARB;
#pragma unroll
        for (int i = 0; i < 4; ++i) {
            const int c16 = (tid & 3) * 4 + i;
            const uint32_t d = base + c16 * 16;
            cpa16(d, kh + c16 * 8);
            cpa16(d + AT_COMP, kl + c16 * 8);
            cpa16(d + 2 * AT_COMP, vh + c16 * 8);
            cpa16(d + 3 * AT_COMP, vl + c16 * 8);
        }
        cpa_commit();
    };

    issue_tile(0, 0);

    for (int t = 0; t < n_t; ++t) {
        const int s = t & 1;
        if (t + 1 < n_t) { issue_tile(t + 1, s ^ 1); cpa_wait1(); }
        else cpa_wait0();
        __syncthreads();

        const uint32_t Khi_s = STG0 + s * AT_STG;
        const uint32_t Klo_s = Khi_s + AT_COMP;
        const uint32_t Vhi_s = Khi_s + 2 * AT_COMP;
        const uint32_t Vlo_s = Khi_s + 3 * AT_COMP;

        // ---- QK^T: 16q x 16keys, K=[s][d] rows, B via non-trans ldsm ----
        float sf[2][4];
#pragma unroll
        for (int nt = 0; nt < 2; ++nt)
#pragma unroll
            for (int e = 0; e < 4; ++e) sf[nt][e] = 0.0f;

#pragma unroll
        for (int ks = 0; ks < 8; ++ks) {
            const uint32_t ka = (uint32_t)((sp * 16 + a_r) * ARB + ks * 32 + a_kb);
            uint32_t bh[4], bl[4];
            ldsm4(bh, Khi_s + ka);
            ldsm4(bl, Klo_s + ka);
            mma_bf(sf[0], qh[ks], bh[0], bh[2]);
            mma_bf(sf[1], qh[ks], bh[1], bh[3]);
            mma_bf(sf[0], qh[ks], bl[0], bl[2]);
            mma_bf(sf[1], qh[ks], bl[1], bl[3]);
            mma_bf(sf[0], ql[ks], bh[0], bh[2]);
            mma_bf(sf[1], ql[ks], bh[1], bh[3]);
        }

        // ---- mask (tail tiles only) ----
        const int colbase = t * 64 + sp * 16;
        if (colbase + 15 > wlim) {
            const int c0 = colbase + (lane & 3) * 2;
#pragma unroll
            for (int nt = 0; nt < 2; ++nt) {
                const int cA = c0 + nt * 8, cB = cA + 1;
                if (cA > lim0) sf[nt][0] = -1e30f;
                if (cB > lim0) sf[nt][1] = -1e30f;
                if (cA > lim1) sf[nt][2] = -1e30f;
                if (cB > lim1) sf[nt][3] = -1e30f;
            }
        }

        // ---- online softmax (rows l/4 and l/4+8; 4 lanes per row) ----
        float rm0 = fmaxf(fmaxf(sf[0][0], sf[0][1]), fmaxf(sf[1][0], sf[1][1]));
        float rm1 = fmaxf(fmaxf(sf[0][2], sf[0][3]), fmaxf(sf[1][2], sf[1][3]));
        rm0 = fmaxf(rm0, __shfl_xor_sync(0xffffffffu, rm0, 1));
        rm0 = fmaxf(rm0, __shfl_xor_sync(0xffffffffu, rm0, 2));
        rm1 = fmaxf(rm1, __shfl_xor_sync(0xffffffffu, rm1, 1));
        rm1 = fmaxf(rm1, __shfl_xor_sync(0xffffffffu, rm1, 2));
        const float mt0 = fmaxf(m0, rm0), mt1 = fmaxf(m1, rm1);
        const float al0 = __expf(m0 - mt0), al1 = __expf(m1 - mt1);
        m0 = mt0; m1 = mt1;

        float p[2][4];
#pragma unroll
        for (int nt = 0; nt < 2; ++nt) {
            p[nt][0] = __expf(sf[nt][0] - mt0);
            p[nt][1] = __expf(sf[nt][1] - mt0);
            p[nt][2] = __expf(sf[nt][2] - mt1);
            p[nt][3] = __expf(sf[nt][3] - mt1);
        }
        float rs0 = p[0][0] + p[0][1] + p[1][0] + p[1][1];
        float rs1 = p[0][2] + p[0][3] + p[1][2] + p[1][3];
        rs0 += __shfl_xor_sync(0xffffffffu, rs0, 1);
        rs0 += __shfl_xor_sync(0xffffffffu, rs0, 2);
        rs1 += __shfl_xor_sync(0xffffffffu, rs1, 1);
        rs1 += __shfl_xor_sync(0xffffffffu, rs1, 2);
        l0 = l0 * al0 + rs0;
        l1 = l1 * al1 + rs1;

        if (__any_sync(0xffffffffu, (al0 < 1.0f) | (al1 < 1.0f))) {
#pragma unroll
            for (int nt = 0; nt < 16; ++nt) {
                o[nt][0] *= al0; o[nt][1] *= al0;
                o[nt][2] *= al1; o[nt][3] *= al1;
            }
        }

        // ---- P fragments (A operand for PV): FA2 layout identity ----
        uint32_t pah[4], pal[4];
        split2(p[0][0], p[0][1], pah[0], pal[0]);
        split2(p[0][2], p[0][3], pah[1], pal[1]);
        split2(p[1][0], p[1][1], pah[2], pal[2]);
        split2(p[1][2], p[1][3], pah[3], pal[3]);

        // ---- PV: k=16 keys, n=128 d; V=[s][d] rows, B via trans ldsm ----
#pragma unroll
        for (int g = 0; g < 8; ++g) {
            const uint32_t va = (uint32_t)((sp * 16 + b_kr) * ARB + g * 32 + b_nb);
            uint32_t vh[4], vl[4];
            ldsm4t(vh, Vhi_s + va);
            ldsm4t(vl, Vlo_s + va);
            mma_bf(o[2 * g],     pah, vh[0], vh[2]);
            mma_bf(o[2 * g + 1], pah, vh[1], vh[3]);
            mma_bf(o[2 * g],     pah, vl[0], vl[2]);
            mma_bf(o[2 * g + 1], pah, vl[1], vl[3]);
            mma_bf(o[2 * g],     pal, vh[0], vh[2]);
            mma_bf(o[2 * g + 1], pal, vh[1], vh[3]);
        }
        __syncthreads();
    }

    // ---- merge: write per-warp (O, m, l) to smem, reduce across sp ----
    {
        const uint32_t ob = sb + wid * 8192;   // 16 rows x 512B
        const int r0 = lane >> 2, c0 = (lane & 3) * 2;
#pragma unroll
        for (int nt = 0; nt < 16; ++nt) {
            *(float2*)(asmem + (wid * 8192) + r0 * 512 + (nt * 8 + c0) * 4) =
                make_float2(o[nt][0], o[nt][1]);
            *(float2*)(asmem + (wid * 8192) + (r0 + 8) * 512 + (nt * 8 + c0) * 4) =
                make_float2(o[nt][2], o[nt][3]);
        }
        if ((lane & 3) == 0) {
            *(float2*)(asmem + 65536 + (wid * 16 + r0) * 8)     = make_float2(m0, l0);
            *(float2*)(asmem + 65536 + (wid * 16 + r0 + 8) * 8) = make_float2(m1, l1);
        }
        (void)ob;
    }
    __syncthreads();

    {
        const int row = tid >> 3;            // 0..31
        const int d0  = (tid & 7) * 16;
        const int mg2 = row >> 4, rr = row & 15;
        float mw[4], lw[4];
#pragma unroll
        for (int i = 0; i < 4; ++i) {
            float2 ml = *(const float2*)(asmem + 65536 + ((i * 2 + mg2) * 16 + rr) * 8);
            mw[i] = ml.x; lw[i] = ml.y;
        }
        float M = fmaxf(fmaxf(mw[0], mw[1]), fmaxf(mw[2], mw[3]));
        float wgt[4], L = 0.0f;
#pragma unroll
        for (int i = 0; i < 4; ++i) { wgt[i] = __expf(mw[i] - M); L += wgt[i] * lw[i]; }
        const float inv = 1.0f / L;

        float accv[16];
#pragma unroll
        for (int j = 0; j < 16; ++j) accv[j] = 0.0f;
#pragma unroll
        for (int i = 0; i < 4; ++i) {
            const float* op = (const float*)(asmem + (i * 2 + mg2) * 8192 + rr * 512 + d0 * 4);
#pragma unroll
            for (int j = 0; j < 16; ++j) accv[j] += wgt[i] * op[j];
        }
        float* dst = O + (size_t)(b * L_ + q0 + row) * D_ + h * 128 + d0;
#pragma unroll
        for (int j = 0; j < 4; ++j) {
            *(float4*)(dst + 4 * j) = make_float4(accv[4 * j] * inv, accv[4 * j + 1] * inv,
                                                  accv[4 * j + 2] * inv, accv[4 * j + 3] * inv);
        }
    }
}

// ---------------------------------------------------------------------------
extern "C" void kernel_launch(void* const* d_in, const int* in_sizes, int n_in,
                              void* d_out, int out_size) {
    const float* x  = (const float*)d_in[0];
    const float* ck = (const float*)d_in[1];
    const float* cv = (const float*)d_in[2];
    const float* Wq = (const float*)d_in[3];
    const float* Wk = (const float*)d_in[4];
    const float* Wv = (const float*)d_in[5];
    const float* Wo = (const float*)d_in[6];
    const float* qw = (const float*)d_in[7];
    const float* kw = (const float*)d_in[8];
    float* out = (float*)d_out;

    void *pq, *pk, *pv, *po, *pwh, *pwl, *pxh, *pxl, *poh, *pol;
    void *pckh, *pckl, *pcvh, *pcvl, *pnkh, *pnkl, *pnvh, *pnvl;
    cudaGetSymbolAddress(&pq, g_q);
    cudaGetSymbolAddress(&pk, g_k);
    cudaGetSymbolAddress(&pv, g_v);
    cudaGetSymbolAddress(&po, g_o);
    cudaGetSymbolAddress(&pwh, g_whi);
    cudaGetSymbolAddress(&pwl, g_wlo);
    cudaGetSymbolAddress(&pxh, g_xhi);
    cudaGetSymbolAddress(&pxl, g_xlo);
    cudaGetSymbolAddress(&poh, g_ohi);
    cudaGetSymbolAddress(&pol, g_olo);
    cudaGetSymbolAddress(&pckh, g_ckhi);
    cudaGetSymbolAddress(&pckl, g_cklo);
    cudaGetSymbolAddress(&pcvh, g_cvhi);
    cudaGetSymbolAddress(&pcvl, g_cvlo);
    cudaGetSymbolAddress(&pnkh, g_nkhi);
    cudaGetSymbolAddress(&pnkl, g_nklo);
    cudaGetSymbolAddress(&pnvh, g_nvhi);
    cudaGetSymbolAddress(&pnvl, g_nvlo);

    float* Qb = (float*)pq;
    float* Kb = (float*)pk;
    float* Vb = (float*)pv;
    float* Ob = (float*)po;
    __nv_bfloat16* Whi = (__nv_bfloat16*)pwh;
    __nv_bfloat16* Wlo = (__nv_bfloat16*)pwl;
    __nv_bfloat16* Xhi = (__nv_bfloat16*)pxh;
    __nv_bfloat16* Xlo = (__nv_bfloat16*)pxl;
    __nv_bfloat16* Ohi = (__nv_bfloat16*)poh;
    __nv_bfloat16* Olo = (__nv_bfloat16*)pol;

    cudaFuncSetAttribute(gemm_mma, cudaFuncAttributeMaxDynamicSharedMemorySize, SMEMT);
    cudaFuncSetAttribute(attn_mma, cudaFuncAttributeMaxDynamicSharedMemorySize, ATT_SMEM);

    const int cache_blocks = (int)(CACHE_E / 2048);

    // 0: split cache K (independent — placed first so gemm lands at capture idx 3)
    cvt_x<<<cache_blocks, 256>>>(ck, (__nv_bfloat16*)pckh, (__nv_bfloat16*)pckl);
    // 1-2: weight + x conversion
    cvt_w<<<dim3(DD / 2048, 4), 256>>>(Wq, Wk, Wv, Wo, Whi, Wlo);
    cvt_x<<<(M_ * D_) / 2048, 256>>>(x, Xhi, Xlo);
    // 3: QKV projection  (ncu capture target)
    gemm_mma<<<dim3(D_ / 128, M_ / 128, 3), 256, SMEMT>>>(Xhi, Xlo, Whi, Wlo, 0, Qb, Kb, Vb);
    // 4: split cache V
    cvt_x<<<cache_blocks, 256>>>(cv, (__nv_bfloat16*)pcvh, (__nv_bfloat16*)pcvl);
    // 5-6: per-head rmsnorm
    rmsnorm_k<<<(M_ * H_) / 8, 256>>>(Qb, qw);
    rmsnorm_k<<<(M_ * H_) / 8, 256>>>(Kb, kw);
    // 7-8: split new K/V
    cvt_x<<<(M_ * D_) / 2048, 256>>>(Kb, (__nv_bfloat16*)pnkh, (__nv_bfloat16*)pnkl);
    cvt_x<<<(M_ * D_) / 2048, 256>>>(Vb, (__nv_bfloat16*)pnvh, (__nv_bfloat16*)pnvl);
    // 9: attention (tensor cores)
    attn_mma<<<dim3(L_ / 32, H_, B_), 256, ATT_SMEM>>>(
        Qb,
        (const __nv_bfloat16*)pckh, (const __nv_bfloat16*)pckl,
        (const __nv_bfloat16*)pcvh, (const __nv_bfloat16*)pcvl,
        (const __nv_bfloat16*)pnkh, (const __nv_bfloat16*)pnkl,
        (const __nv_bfloat16*)pnvh, (const __nv_bfloat16*)pnvl,
        Ob);
    // 10-11: output projection
    cvt_x<<<(M_ * D_) / 2048, 256>>>(Ob, Ohi, Olo);
    gemm_mma<<<dim3(D_ / 128, M_ / 128, 1), 256, SMEMT>>>(Ohi, Olo, Whi, Wlo, 3, out, out, out);
}

// round 9
// speedup vs baseline: 7.7886x; 1.1257x over previous
#include <cuda_runtime.h>
#include <cuda_bf16.h>
#include <cstdint>

// Problem constants
constexpr int B_  = 2;
constexpr int L_  = 256;
constexpr int D_  = 4096;
constexpr int H_  = 32;
constexpr int Dh_ = 128;
constexpr int S_  = 4224;
constexpr int SINK_ = 128;
constexpr int WINS_ = S_ - L_;     // 3968
constexpr int M_  = B_ * L_;       // 512
constexpr size_t DD = (size_t)D_ * D_;
constexpr size_t CACHE_E = (size_t)B_ * S_ * H_ * Dh_;

// GEMM tiling
constexpr int BK = 32;
constexpr int NCHUNK = D_ / BK;        // 128
constexpr int A_ROW_B = 80;
constexpr int B_ROW_B = 272;
constexpr int A_TILE = 128 * A_ROW_B;  // 10240
constexpr int B_TILE = BK * B_ROW_B;   // 8704
constexpr int STAGE  = 2 * A_TILE + 2 * B_TILE;  // 37888
constexpr int SMEMT  = 2 * STAGE;      // 75776

// Attention smem layout (bytes): 64 q rows, 32-key tiles, double-buffered
constexpr int ARB = 272;
constexpr int AQ_COMP = 64 * ARB;              // 17408 (Q hi or lo)
constexpr int AT_COMP = 32 * ARB;              // 8704 per K/V component
constexpr int AT_STG  = 4 * AT_COMP;           // 34816 (Khi,Klo,Vhi,Vlo)
constexpr int ATT_SMEM = 2 * AQ_COMP + 2 * AT_STG;  // 104448

// scratch
__device__ float g_q[M_ * D_];
__device__ float g_k[M_ * D_];
__device__ float g_v[M_ * D_];
__device__ float g_o[M_ * D_];
__device__ __nv_bfloat16 g_whi[4 * DD];
__device__ __nv_bfloat16 g_wlo[4 * DD];
__device__ __nv_bfloat16 g_xhi[M_ * D_];
__device__ __nv_bfloat16 g_xlo[M_ * D_];
__device__ __nv_bfloat16 g_ohi[M_ * D_];
__device__ __nv_bfloat16 g_olo[M_ * D_];
__device__ __nv_bfloat16 g_ckhi[CACHE_E];
__device__ __nv_bfloat16 g_cklo[CACHE_E];
__device__ __nv_bfloat16 g_cvhi[CACHE_E];
__device__ __nv_bfloat16 g_cvlo[CACHE_E];
__device__ __nv_bfloat16 g_nkhi[M_ * D_];
__device__ __nv_bfloat16 g_nklo[M_ * D_];
__device__ __nv_bfloat16 g_nvhi[M_ * D_];
__device__ __nv_bfloat16 g_nvlo[M_ * D_];

// ---- helpers ----
__device__ __forceinline__ uint32_t smem_u32(const void* p) {
    uint32_t a;
    asm("{ .reg .u64 t; cvta.to.shared.u64 t, %1; cvt.u32.u64 %0, t; }" : "=r"(a) : "l"(p));
    return a;
}
__device__ __forceinline__ void ldsm4(uint32_t* r, uint32_t a) {
    asm volatile("ldmatrix.sync.aligned.m8n8.x4.shared.b16 {%0,%1,%2,%3},[%4];"
                 : "=r"(r[0]), "=r"(r[1]), "=r"(r[2]), "=r"(r[3]) : "r"(a));
}
__device__ __forceinline__ void ldsm4t(uint32_t* r, uint32_t a) {
    asm volatile("ldmatrix.sync.aligned.m8n8.x4.trans.shared.b16 {%0,%1,%2,%3},[%4];"
                 : "=r"(r[0]), "=r"(r[1]), "=r"(r[2]), "=r"(r[3]) : "r"(a));
}
__device__ __forceinline__ void mma_bf(float* c, const uint32_t* a, uint32_t b0, uint32_t b1) {
    asm volatile(
        "mma.sync.aligned.m16n8k16.row.col.f32.bf16.bf16.f32 "
        "{%0,%1,%2,%3},{%4,%5,%6,%7},{%8,%9},{%0,%1,%2,%3};"
        : "+f"(c[0]), "+f"(c[1]), "+f"(c[2]), "+f"(c[3])
        : "r"(a[0]), "r"(a[1]), "r"(a[2]), "r"(a[3]), "r"(b0), "r"(b1));
}
__device__ __forceinline__ void split2(float x, float y, uint32_t& hi, uint32_t& lo) {
    __nv_bfloat16 hx = __float2bfloat16_rn(x);
    __nv_bfloat16 hy = __float2bfloat16_rn(y);
    __nv_bfloat16 lx = __float2bfloat16_rn(x - __bfloat162float(hx));
    __nv_bfloat16 ly = __float2bfloat16_rn(y - __bfloat162float(hy));
    hi = (uint32_t)__bfloat16_as_ushort(hx) | ((uint32_t)__bfloat16_as_ushort(hy) << 16);
    lo = (uint32_t)__bfloat16_as_ushort(lx) | ((uint32_t)__bfloat16_as_ushort(ly) << 16);
}
__device__ __forceinline__ void cpa16(uint32_t dst, const void* src) {
    asm volatile("cp.async.ca.shared.global [%0],[%1],16;" :: "r"(dst), "l"(src));
}
__device__ __forceinline__ void cpa_commit() {
    asm volatile("cp.async.commit_group;" ::: "memory");
}
__device__ __forceinline__ void cpa_wait1() {
    asm volatile("cp.async.wait_group 1;" ::: "memory");
}
__device__ __forceinline__ void cpa_wait0() {
    asm volatile("cp.async.wait_group 0;" ::: "memory");
}

// ---------------------------------------------------------------------------
// Split-convert kernels
// ---------------------------------------------------------------------------
__global__ __launch_bounds__(256) void cvt_w(
    const float* __restrict__ w0, const float* __restrict__ w1,
    const float* __restrict__ w2, const float* __restrict__ w3,
    __nv_bfloat16* __restrict__ hi, __nv_bfloat16* __restrict__ lo)
{
    const float* src = (blockIdx.y == 0) ? w0 : (blockIdx.y == 1) ? w1 : (blockIdx.y == 2) ? w2 : w3;
    const size_t base = (size_t)blockIdx.y * DD;
    const size_t i = ((size_t)blockIdx.x * 256 + threadIdx.x) * 8;
    float4 f0 = *(const float4*)(src + i);
    float4 f1 = *(const float4*)(src + i + 4);
    uint4 h, l;
    split2(f0.x, f0.y, h.x, l.x);
    split2(f0.z, f0.w, h.y, l.y);
    split2(f1.x, f1.y, h.z, l.z);
    split2(f1.z, f1.w, h.w, l.w);
    *(uint4*)(hi + base + i) = h;
    *(uint4*)(lo + base + i) = l;
}

__global__ __launch_bounds__(256) void cvt_x(
    const float* __restrict__ src,
    __nv_bfloat16* __restrict__ hi, __nv_bfloat16* __restrict__ lo)
{
    const size_t i = ((size_t)blockIdx.x * 256 + threadIdx.x) * 8;
    float4 f0 = *(const float4*)(src + i);
    float4 f1 = *(const float4*)(src + i + 4);
    uint4 h, l;
    split2(f0.x, f0.y, h.x, l.x);
    split2(f0.z, f0.w, h.y, l.y);
    split2(f1.x, f1.y, h.z, l.z);
    split2(f1.z, f1.w, h.w, l.w);
    *(uint4*)(hi + i) = h;
    *(uint4*)(lo + i) = l;
}

// ---------------------------------------------------------------------------
// mma.sync split-bf16 GEMM (unchanged — at HMMA architectural floor)
// ---------------------------------------------------------------------------
__global__ __launch_bounds__(256, 2) void gemm_mma(
    const __nv_bfloat16* __restrict__ Ahi, const __nv_bfloat16* __restrict__ Alo,
    const __nv_bfloat16* __restrict__ Whi, const __nv_bfloat16* __restrict__ Wlo,
    int wzoff,
    float* __restrict__ C0, float* __restrict__ C1, float* __restrict__ C2)
{
    float* C = (blockIdx.z == 0) ? C0 : (blockIdx.z == 1) ? C1 : C2;
    const size_t woff = (size_t)(blockIdx.z + wzoff) * DD;

    extern __shared__ char smem[];
    const uint32_t sb = smem_u32(smem);
    const int tid  = threadIdx.x;
    const int wid  = tid >> 5;
    const int lane = tid & 31;
    const int wm   = wid & 1;
    const int wn   = wid >> 1;

    const int m0 = blockIdx.y * 128;
    const int n0 = blockIdx.x * 128;

    const __nv_bfloat16* AhiB = Ahi + (size_t)m0 * D_;
    const __nv_bfloat16* AloB = Alo + (size_t)m0 * D_;
    const __nv_bfloat16* WhiB = Whi + woff + n0;
    const __nv_bfloat16* WloB = Wlo + woff + n0;

    float acc[4][4][4];
#pragma unroll
    for (int mt = 0; mt < 4; ++mt)
#pragma unroll
        for (int nt = 0; nt < 4; ++nt)
#pragma unroll
            for (int e = 0; e < 4; ++e) acc[mt][nt][e] = 0.0f;

    const int a_r   = (lane & 7) + ((lane >> 3) & 1) * 8;
    const int a_kb  = (lane >> 4) * 16;
    const int b_kr  = (lane & 7) + (lane >> 4) * 8;
    const int b_nb  = ((lane >> 3) & 1) * 16;

    auto issue_stage = [&](int ch, int s) {
        const uint32_t stA = sb + s * STAGE;
        const uint32_t stB = stA + 2 * A_TILE;
#pragma unroll
        for (int i = 0; i < 2; ++i) {
            const int c = tid * 2 + i;
            const int ar = c >> 2, akc = c & 3;
            const size_t aoff = (size_t)ar * D_ + ch * BK + akc * 8;
            const uint32_t adst = stA + ar * A_ROW_B + akc * 16;
            cpa16(adst, AhiB + aoff);
            cpa16(adst + A_TILE, AloB + aoff);
            const int br = c >> 4, bnc = c & 15;
            const size_t boff = (size_t)(ch * BK + br) * D_ + bnc * 8;
            const uint32_t bdst = stB + br * B_ROW_B + bnc * 16;
            cpa16(bdst, WhiB + boff);
            cpa16(bdst + B_TILE, WloB + boff);
        }
        cpa_commit();
    };

    issue_stage(0, 0);

    for (int ch = 0; ch < NCHUNK; ++ch) {
        const int s = ch & 1;
        if (ch + 1 < NCHUNK) { issue_stage(ch + 1, s ^ 1); cpa_wait1(); }
        else cpa_wait0();
        __syncthreads();

        const uint32_t Ah = sb + s * STAGE;
        const uint32_t Al = Ah + A_TILE;
        const uint32_t Bh = Ah + 2 * A_TILE;
        const uint32_t Bl = Bh + B_TILE;

#pragma unroll
        for (int kc = 0; kc < 2; ++kc) {
            uint32_t ah[4][4], al[4][4];
            uint32_t bh[4][2], bl[4][2];
            const uint32_t a_addr = (uint32_t)((wm * 64 + a_r) * A_ROW_B + kc * 32 + a_kb);
#pragma unroll
            for (int mt = 0; mt < 4; ++mt) {
                ldsm4(ah[mt], Ah + a_addr + mt * 16 * A_ROW_B);
                ldsm4(al[mt], Al + a_addr + mt * 16 * A_ROW_B);
            }
            const uint32_t b_addr = (uint32_t)((kc * 16 + b_kr) * B_ROW_B + (wn * 32) * 2 + b_nb);
#pragma unroll
            for (int p = 0; p < 2; ++p) {
                uint32_t rh[4], rl[4];
                ldsm4t(rh, Bh + b_addr + p * 32);
                ldsm4t(rl, Bl + b_addr + p * 32);
                bh[2 * p][0] = rh[0]; bh[2 * p][1] = rh[2];
                bh[2 * p + 1][0] = rh[1]; bh[2 * p + 1][1] = rh[3];
                bl[2 * p][0] = rl[0]; bl[2 * p][1] = rl[2];
                bl[2 * p + 1][0] = rl[1]; bl[2 * p + 1][1] = rl[3];
            }
#pragma unroll
            for (int mt = 0; mt < 4; ++mt)
#pragma unroll
                for (int nt = 0; nt < 4; ++nt)
                    mma_bf(acc[mt][nt], ah[mt], bh[nt][0], bh[nt][1]);
#pragma unroll
            for (int mt = 0; mt < 4; ++mt)
#pragma unroll
                for (int nt = 0; nt < 4; ++nt)
                    mma_bf(acc[mt][nt], ah[mt], bl[nt][0], bl[nt][1]);
#pragma unroll
            for (int mt = 0; mt < 4; ++mt)
#pragma unroll
                for (int nt = 0; nt < 4; ++nt)
                    mma_bf(acc[mt][nt], al[mt], bh[nt][0], bh[nt][1]);
        }
        __syncthreads();
    }

    const int gr = lane >> 2;
    const int gc = lane & 3;
#pragma unroll
    for (int mt = 0; mt < 4; ++mt) {
        const int row = m0 + wm * 64 + mt * 16 + gr;
        float* c0 = C + (size_t)row * D_ + n0 + wn * 32;
        float* c1 = C + (size_t)(row + 8) * D_ + n0 + wn * 32;
#pragma unroll
        for (int nt = 0; nt < 4; ++nt) {
            *(float2*)(c0 + nt * 8 + gc * 2) = make_float2(acc[mt][nt][0], acc[mt][nt][1]);
            *(float2*)(c1 + nt * 8 + gc * 2) = make_float2(acc[mt][nt][2], acc[mt][nt][3]);
        }
    }
}

// ---------------------------------------------------------------------------
__global__ __launch_bounds__(256) void rmsnorm_k(float* __restrict__ X,
                                                 const float* __restrict__ w) {
    const int row  = (blockIdx.x * 256 + threadIdx.x) >> 5;
    const int lane = threadIdx.x & 31;
    float* p = X + (size_t)row * 128 + lane * 4;
    float4 v = *(float4*)p;
    float ss = v.x * v.x + v.y * v.y + v.z * v.z + v.w * v.w;
#pragma unroll
    for (int o = 16; o; o >>= 1) ss += __shfl_xor_sync(0xffffffffu, ss, o);
    float r = rsqrtf(ss * (1.0f / 128.0f) + 1e-6f);
    float4 wv = *(const float4*)(w + lane * 4);
    v.x *= r * wv.x; v.y *= r * wv.y; v.z *= r * wv.z; v.w *= r * wv.w;
    *(float4*)p = v;
}

// rmsnorm + split in one pass (for K)
__global__ __launch_bounds__(256) void rmsnorm_split(const float* __restrict__ X,
                                                     const float* __restrict__ w,
                                                     __nv_bfloat16* __restrict__ hi,
                                                     __nv_bfloat16* __restrict__ lo) {
    const int row  = (blockIdx.x * 256 + threadIdx.x) >> 5;
    const int lane = threadIdx.x & 31;
    const float* p = X + (size_t)row * 128 + lane * 4;
    float4 v = *(const float4*)p;
    float ss = v.x * v.x + v.y * v.y + v.z * v.z + v.w * v.w;
#pragma unroll
    for (int o = 16; o; o >>= 1) ss += __shfl_xor_sync(0xffffffffu, ss, o);
    float r = rsqrtf(ss * (1.0f / 128.0f) + 1e-6f);
    float4 wv = *(const float4*)(w + lane * 4);
    v.x *= r * wv.x; v.y *= r * wv.y; v.z *= r * wv.z; v.w *= r * wv.w;
    uint32_t h0, l0, h1, l1;
    split2(v.x, v.y, h0, l0);
    split2(v.z, v.w, h1, l1);
    *(uint2*)(hi + (size_t)row * 128 + lane * 4) = make_uint2(h0, h1);
    *(uint2*)(lo + (size_t)row * 128 + lane * 4) = make_uint2(l0, l1);
}

// ---------------------------------------------------------------------------
// MMA flash attention. CTA = 64 queries (one head). 8 warps = 4 q-groups(mg)
// x 2 key-splits(sp). 32-key tiles double-buffered. Q frags reloaded from
// smem per tile (low regs -> 2 CTAs/SM). Split-bf16 (3 MMAs) QK and PV.
// ---------------------------------------------------------------------------
__global__ __launch_bounds__(256, 2) void attn_mma(
    const float* __restrict__ Qf,
    const __nv_bfloat16* __restrict__ CKhi, const __nv_bfloat16* __restrict__ CKlo,
    const __nv_bfloat16* __restrict__ CVhi, const __nv_bfloat16* __restrict__ CVlo,
    const __nv_bfloat16* __restrict__ NKhi, const __nv_bfloat16* __restrict__ NKlo,
    const __nv_bfloat16* __restrict__ NVhi, const __nv_bfloat16* __restrict__ NVlo,
    float* __restrict__ O)
{
    extern __shared__ char asmem[];
    const uint32_t sb = smem_u32(asmem);

    const int tid  = threadIdx.x;
    const int wid  = tid >> 5;
    const int lane = tid & 31;
    const int mg   = wid >> 1;        // q group 0..3 (16 q each)
    const int sp   = wid & 1;         // key split 0..1 (16 keys each)
    const int h    = blockIdx.y;
    const int b    = blockIdx.z;
    const int q0   = blockIdx.x * 64;

    const float scale = 0.08838834764831845f;

    const uint32_t Qhi_o = sb;
    const uint32_t Qlo_o = sb + AQ_COMP;
    const uint32_t STG0  = sb + 2 * AQ_COMP;

    // ---- fill Q (64 rows, pre-scaled, split) ----
    {
        const int row = tid >> 2;
        const int d0  = (tid & 3) * 32;
        const float* qp = Qf + ((size_t)(b * L_ + q0 + row) * H_ + h) * Dh_ + d0;
        const uint32_t dst = (uint32_t)(row * ARB + d0 * 2);
#pragma unroll
        for (int i = 0; i < 16; ++i) {
            float2 f = *(const float2*)(qp + 2 * i);
            uint32_t hreg, lreg;
            split2(f.x * scale, f.y * scale, hreg, lreg);
            *(uint32_t*)(asmem + dst + 4 * i) = hreg;
            *(uint32_t*)(asmem + AQ_COMP + dst + 4 * i) = lreg;
        }
    }
    __syncthreads();

    const int a_r  = (lane & 7) + ((lane >> 3) & 1) * 8;
    const int a_kb = (lane >> 4) * 16;
    const int b_kr = (lane & 7) + (lane >> 4) * 8;
    const int b_nb = ((lane >> 3) & 1) * 16;

    float o[16][4];
#pragma unroll
    for (int nt = 0; nt < 16; ++nt)
#pragma unroll
        for (int e = 0; e < 4; ++e) o[nt][e] = 0.0f;
    float m0 = -1e30f, m1 = -1e30f, l0 = 0.0f, l1 = 0.0f;

    const int wlim = WINS_ + q0 + mg * 16;
    const int lim0 = wlim + (lane >> 2);
    const int lim1 = lim0 + 8;
    const int n_t  = (WINS_ + q0 + 64) / 32;   // always divisible

    auto issue_tile = [&](int t, int s) {
        const int sg = t * 32 + (tid >> 3);
        const __nv_bfloat16 *kh, *kl, *vh, *vl;
        if (sg < WINS_) {
            const int src = (sg < SINK_) ? sg : sg + L_;
            const size_t off = (((size_t)b * S_ + src) * H_ + h) * Dh_;
            kh = CKhi + off; kl = CKlo + off; vh = CVhi + off; vl = CVlo + off;
        } else {
            const size_t off = (((size_t)b * L_ + (sg - WINS_)) * H_ + h) * Dh_;
            kh = NKhi + off; kl = NKlo + off; vh = NVhi + off; vl = NVlo + off;
        }
        const uint32_t base = STG0 + s * AT_STG + (tid >> 3) * ARB;
#pragma unroll
        for (int i = 0; i < 2; ++i) {
            const int c16 = (tid & 7) * 2 + i;
            const uint32_t d = base + c16 * 16;
            cpa16(d, kh + c16 * 8);
            cpa16(d + AT_COMP, kl + c16 * 8);
            cpa16(d + 2 * AT_COMP, vh + c16 * 8);
            cpa16(d + 3 * AT_COMP, vl + c16 * 8);
        }
        cpa_commit();
    };

    issue_tile(0, 0);

    for (int t = 0; t < n_t; ++t) {
        const int s = t & 1;
        cpa_wait0();
        __syncthreads();
        if (t + 1 < n_t) issue_tile(t + 1, s ^ 1);

        const int colbase = t * 32 + sp * 16;
        if (colbase <= wlim + 15) {
            const uint32_t Khi_s = STG0 + s * AT_STG;
            const uint32_t Klo_s = Khi_s + AT_COMP;
            const uint32_t Vhi_s = Khi_s + 2 * AT_COMP;
            const uint32_t Vlo_s = Khi_s + 3 * AT_COMP;

            // ---- QK^T ----
            float sf[2][4];
#pragma unroll
            for (int nt = 0; nt < 2; ++nt)
#pragma unroll
                for (int e = 0; e < 4; ++e) sf[nt][e] = 0.0f;

#pragma unroll
            for (int ks = 0; ks < 8; ++ks) {
                const uint32_t qa = (uint32_t)((mg * 16 + a_r) * ARB + ks * 32 + a_kb);
                const uint32_t ka = (uint32_t)((sp * 16 + a_r) * ARB + ks * 32 + a_kb);
                uint32_t qh4[4], ql4[4], kh4[4], kl4[4];
                ldsm4(qh4, Qhi_o + qa);
                ldsm4(ql4, Qlo_o + qa);
                ldsm4(kh4, Khi_s + ka);
                ldsm4(kl4, Klo_s + ka);
                mma_bf(sf[0], qh4, kh4[0], kh4[2]);
                mma_bf(sf[1], qh4, kh4[1], kh4[3]);
                mma_bf(sf[0], qh4, kl4[0], kl4[2]);
                mma_bf(sf[1], qh4, kl4[1], kl4[3]);
                mma_bf(sf[0], ql4, kh4[0], kh4[2]);
                mma_bf(sf[1], ql4, kh4[1], kh4[3]);
            }

            // ---- mask ----
            if (colbase + 15 > wlim) {
                const int c0m = colbase + (lane & 3) * 2;
#pragma unroll
                for (int nt = 0; nt < 2; ++nt) {
                    const int cA = c0m + nt * 8, cB = cA + 1;
                    if (cA > lim0) sf[nt][0] = -1e30f;
                    if (cB > lim0) sf[nt][1] = -1e30f;
                    if (cA > lim1) sf[nt][2] = -1e30f;
                    if (cB > lim1) sf[nt][3] = -1e30f;
                }
            }

            // ---- online softmax ----
            float rm0 = fmaxf(fmaxf(sf[0][0], sf[0][1]), fmaxf(sf[1][0], sf[1][1]));
            float rm1 = fmaxf(fmaxf(sf[0][2], sf[0][3]), fmaxf(sf[1][2], sf[1][3]));
            rm0 = fmaxf(rm0, __shfl_xor_sync(0xffffffffu, rm0, 1));
            rm0 = fmaxf(rm0, __shfl_xor_sync(0xffffffffu, rm0, 2));
            rm1 = fmaxf(rm1, __shfl_xor_sync(0xffffffffu, rm1, 1));
            rm1 = fmaxf(rm1, __shfl_xor_sync(0xffffffffu, rm1, 2));
            const float mt0 = fmaxf(m0, rm0), mt1 = fmaxf(m1, rm1);
            const float al0 = __expf(m0 - mt0), al1 = __expf(m1 - mt1);
            m0 = mt0; m1 = mt1;

            float p[2][4];
#pragma unroll
            for (int nt = 0; nt < 2; ++nt) {
                p[nt][0] = __expf(sf[nt][0] - mt0);
                p[nt][1] = __expf(sf[nt][1] - mt0);
                p[nt][2] = __expf(sf[nt][2] - mt1);
                p[nt][3] = __expf(sf[nt][3] - mt1);
            }
            float rs0 = p[0][0] + p[0][1] + p[1][0] + p[1][1];
            float rs1 = p[0][2] + p[0][3] + p[1][2] + p[1][3];
            rs0 += __shfl_xor_sync(0xffffffffu, rs0, 1);
            rs0 += __shfl_xor_sync(0xffffffffu, rs0, 2);
            rs1 += __shfl_xor_sync(0xffffffffu, rs1, 1);
            rs1 += __shfl_xor_sync(0xffffffffu, rs1, 2);
            l0 = l0 * al0 + rs0;
            l1 = l1 * al1 + rs1;

            if (__any_sync(0xffffffffu, (al0 < 1.0f) | (al1 < 1.0f))) {
#pragma unroll
                for (int nt = 0; nt < 16; ++nt) {
                    o[nt][0] *= al0; o[nt][1] *= al0;
                    o[nt][2] *= al1; o[nt][3] *= al1;
                }
            }

            // ---- P fragments ----
            uint32_t pah[4], pal[4];
            split2(p[0][0], p[0][1], pah[0], pal[0]);
            split2(p[0][2], p[0][3], pah[1], pal[1]);
            split2(p[1][0], p[1][1], pah[2], pal[2]);
            split2(p[1][2], p[1][3], pah[3], pal[3]);

            // ---- PV ----
#pragma unroll
            for (int g = 0; g < 8; ++g) {
                const uint32_t va = (uint32_t)((sp * 16 + b_kr) * ARB + g * 32 + b_nb);
                uint32_t vh4[4], vl4[4];
                ldsm4t(vh4, Vhi_s + va);
                ldsm4t(vl4, Vlo_s + va);
                mma_bf(o[2 * g],     pah, vh4[0], vh4[2]);
                mma_bf(o[2 * g + 1], pah, vh4[1], vh4[3]);
                mma_bf(o[2 * g],     pah, vl4[0], vl4[2]);
                mma_bf(o[2 * g + 1], pah, vl4[1], vl4[3]);
                mma_bf(o[2 * g],     pal, vh4[0], vh4[2]);
                mma_bf(o[2 * g + 1], pal, vh4[1], vh4[3]);
            }
        }
    }

    // ---- merge across the 2 sp warps of each mg group ----
    __syncthreads();
    {
        const int r0 = lane >> 2, c0 = (lane & 3) * 2;
#pragma unroll
        for (int nt = 0; nt < 16; ++nt) {
            *(float2*)(asmem + wid * 8192 + r0 * 512 + (nt * 8 + c0) * 4) =
                make_float2(o[nt][0], o[nt][1]);
            *(float2*)(asmem + wid * 8192 + (r0 + 8) * 512 + (nt * 8 + c0) * 4) =
                make_float2(o[nt][2], o[nt][3]);
        }
        if ((lane & 3) == 0) {
            *(float2*)(asmem + 65536 + (wid * 16 + r0) * 8)     = make_float2(m0, l0);
            *(float2*)(asmem + 65536 + (wid * 16 + r0 + 8) * 8) = make_float2(m1, l1);
        }
    }
    __syncthreads();

    {
        const int row = tid >> 2;             // 0..63
        const int d0  = (tid & 3) * 32;
        const int mg2 = row >> 4, rr = row & 15;
        float2 ml0 = *(const float2*)(asmem + 65536 + ((2 * mg2) * 16 + rr) * 8);
        float2 ml1 = *(const float2*)(asmem + 65536 + ((2 * mg2 + 1) * 16 + rr) * 8);
        const float M = fmaxf(ml0.x, ml1.x);
        const float w0 = __expf(ml0.x - M), w1 = __expf(ml1.x - M);
        const float inv = 1.0f / (w0 * ml0.y + w1 * ml1.y);
        const float* b0 = (const float*)(asmem + (2 * mg2) * 8192 + rr * 512 + d0 * 4);
        const float* b1 = (const float*)(asmem + (2 * mg2 + 1) * 8192 + rr * 512 + d0 * 4);
        float* dst = O + (size_t)(b * L_ + q0 + row) * D_ + h * 128 + d0;
#pragma unroll
        for (int j = 0; j < 8; ++j) {
            float4 f0 = *(const float4*)(b0 + 4 * j);
            float4 f1 = *(const float4*)(b1 + 4 * j);
            *(float4*)(dst + 4 * j) = make_float4(
                (w0 * f0.x + w1 * f1.x) * inv, (w0 * f0.y + w1 * f1.y) * inv,
                (w0 * f0.z + w1 * f1.z) * inv, (w0 * f0.w + w1 * f1.w) * inv);
        }
    }
}

// ---------------------------------------------------------------------------
extern "C" void kernel_launch(void* const* d_in, const int* in_sizes, int n_in,
                              void* d_out, int out_size) {
    const float* x  = (const float*)d_in[0];
    const float* ck = (const float*)d_in[1];
    const float* cv = (const float*)d_in[2];
    const float* Wq = (const float*)d_in[3];
    const float* Wk = (const float*)d_in[4];
    const float* Wv = (const float*)d_in[5];
    const float* Wo = (const float*)d_in[6];
    const float* qw = (const float*)d_in[7];
    const float* kw = (const float*)d_in[8];
    float* out = (float*)d_out;

    void *pq, *pk, *pv, *po, *pwh, *pwl, *pxh, *pxl, *poh, *pol;
    void *pckh, *pckl, *pcvh, *pcvl, *pnkh, *pnkl, *pnvh, *pnvl;
    cudaGetSymbolAddress(&pq, g_q);
    cudaGetSymbolAddress(&pk, g_k);
    cudaGetSymbolAddress(&pv, g_v);
    cudaGetSymbolAddress(&po, g_o);
    cudaGetSymbolAddress(&pwh, g_whi);
    cudaGetSymbolAddress(&pwl, g_wlo);
    cudaGetSymbolAddress(&pxh, g_xhi);
    cudaGetSymbolAddress(&pxl, g_xlo);
    cudaGetSymbolAddress(&poh, g_ohi);
    cudaGetSymbolAddress(&pol, g_olo);
    cudaGetSymbolAddress(&pckh, g_ckhi);
    cudaGetSymbolAddress(&pckl, g_cklo);
    cudaGetSymbolAddress(&pcvh, g_cvhi);
    cudaGetSymbolAddress(&pcvl, g_cvlo);
    cudaGetSymbolAddress(&pnkh, g_nkhi);
    cudaGetSymbolAddress(&pnkl, g_nklo);
    cudaGetSymbolAddress(&pnvh, g_nvhi);
    cudaGetSymbolAddress(&pnvl, g_nvlo);

    float* Qb = (float*)pq;
    float* Kb = (float*)pk;
    float* Vb = (float*)pv;
    float* Ob = (float*)po;
    __nv_bfloat16* Whi = (__nv_bfloat16*)pwh;
    __nv_bfloat16* Wlo = (__nv_bfloat16*)pwl;
    __nv_bfloat16* Xhi = (__nv_bfloat16*)pxh;
    __nv_bfloat16* Xlo = (__nv_bfloat16*)pxl;
    __nv_bfloat16* Ohi = (__nv_bfloat16*)poh;
    __nv_bfloat16* Olo = (__nv_bfloat16*)pol;

    cudaFuncSetAttribute(gemm_mma, cudaFuncAttributeMaxDynamicSharedMemorySize, SMEMT);
    cudaFuncSetAttribute(attn_mma, cudaFuncAttributeMaxDynamicSharedMemorySize, ATT_SMEM);

    const int cache_blocks = (int)(CACHE_E / 2048);

    cvt_x<<<cache_blocks, 256>>>(ck, (__nv_bfloat16*)pckh, (__nv_bfloat16*)pckl);
    cvt_w<<<dim3(DD / 2048, 4), 256>>>(Wq, Wk, Wv, Wo, Whi, Wlo);
    cvt_x<<<(M_ * D_) / 2048, 256>>>(x, Xhi, Xlo);
    gemm_mma<<<dim3(D_ / 128, M_ / 128, 3), 256, SMEMT>>>(Xhi, Xlo, Whi, Wlo, 0, Qb, Kb, Vb);
    cvt_x<<<cache_blocks, 256>>>(cv, (__nv_bfloat16*)pcvh, (__nv_bfloat16*)pcvl);
    rmsnorm_k<<<(M_ * H_) / 8, 256>>>(Qb, qw);
    rmsnorm_split<<<(M_ * H_) / 8, 256>>>(Kb, kw, (__nv_bfloat16*)pnkh, (__nv_bfloat16*)pnkl);
    cvt_x<<<(M_ * D_) / 2048, 256>>>(Vb, (__nv_bfloat16*)pnvh, (__nv_bfloat16*)pnvl);
    attn_mma<<<dim3(L_ / 64, H_, B_), 256, ATT_SMEM>>>(
        Qb,
        (const __nv_bfloat16*)pckh, (const __nv_bfloat16*)pckl,
        (const __nv_bfloat16*)pcvh, (const __nv_bfloat16*)pcvl,
        (const __nv_bfloat16*)pnkh, (const __nv_bfloat16*)pnkl,
        (const __nv_bfloat16*)pnvh, (const __nv_bfloat16*)pnvl,
        Ob);
    cvt_x<<<(M_ * D_) / 2048, 256>>>(Ob, Ohi, Olo);
    gemm_mma<<<dim3(D_ / 128, M_ / 128, 1), 256, SMEMT>>>(Ohi, Olo, Whi, Wlo, 3, out, out, out);
}

// round 12
// speedup vs baseline: 7.7976x; 1.0011x over previous
#include <cuda_runtime.h>
#include <cuda_bf16.h>
#include <cstdint>

// Problem constants
constexpr int B_  = 2;
constexpr int L_  = 256;
constexpr int D_  = 4096;
constexpr int H_  = 32;
constexpr int Dh_ = 128;
constexpr int S_  = 4224;
constexpr int SINK_ = 128;
constexpr int WINS_ = S_ - L_;     // 3968
constexpr int M_  = B_ * L_;       // 512
constexpr size_t DD = (size_t)D_ * D_;
constexpr size_t CACHE_E = (size_t)B_ * S_ * H_ * Dh_;

// GEMM tiling
constexpr int BK = 32;
constexpr int NCHUNK = D_ / BK;        // 128
constexpr int A_ROW_B = 80;
constexpr int B_ROW_B = 272;
constexpr int A_TILE = 128 * A_ROW_B;  // 10240
constexpr int B_TILE = BK * B_ROW_B;   // 8704
constexpr int STAGE  = 2 * A_TILE + 2 * B_TILE;  // 37888
constexpr int SMEMT  = 2 * STAGE;      // 75776

// Attention smem layout (bytes): 64 q rows, 32-key tiles, double-buffered
// Components per tile: Khi, Klo, Vhi, Vlo (full split — V bf16-only fails accuracy)
constexpr int ARB = 272;
constexpr int AQ_COMP = 64 * ARB;              // 17408 (Q hi or lo)
constexpr int AT_COMP = 32 * ARB;              // 8704 per K/V component
constexpr int AT_STG  = 4 * AT_COMP;           // 34816 (Khi,Klo,Vhi,Vlo)
constexpr int ATT_SMEM = 2 * AQ_COMP + 2 * AT_STG;  // 104448

// scratch
__device__ float g_q[M_ * D_];
__device__ float g_k[M_ * D_];
__device__ float g_v[M_ * D_];
__device__ float g_o[M_ * D_];
__device__ __nv_bfloat16 g_whi[4 * DD];
__device__ __nv_bfloat16 g_wlo[4 * DD];
__device__ __nv_bfloat16 g_xhi[M_ * D_];
__device__ __nv_bfloat16 g_xlo[M_ * D_];
__device__ __nv_bfloat16 g_ohi[M_ * D_];
__device__ __nv_bfloat16 g_olo[M_ * D_];
__device__ __nv_bfloat16 g_ckhi[CACHE_E];
__device__ __nv_bfloat16 g_cklo[CACHE_E];
__device__ __nv_bfloat16 g_cvhi[CACHE_E];
__device__ __nv_bfloat16 g_cvlo[CACHE_E];
__device__ __nv_bfloat16 g_nkhi[M_ * D_];
__device__ __nv_bfloat16 g_nklo[M_ * D_];
__device__ __nv_bfloat16 g_nvhi[M_ * D_];
__device__ __nv_bfloat16 g_nvlo[M_ * D_];

// ---- helpers ----
__device__ __forceinline__ uint32_t smem_u32(const void* p) {
    uint32_t a;
    asm("{ .reg .u64 t; cvta.to.shared.u64 t, %1; cvt.u32.u64 %0, t; }" : "=r"(a) : "l"(p));
    return a;
}
__device__ __forceinline__ void ldsm4(uint32_t* r, uint32_t a) {
    asm volatile("ldmatrix.sync.aligned.m8n8.x4.shared.b16 {%0,%1,%2,%3},[%4];"
                 : "=r"(r[0]), "=r"(r[1]), "=r"(r[2]), "=r"(r[3]) : "r"(a));
}
__device__ __forceinline__ void ldsm4t(uint32_t* r, uint32_t a) {
    asm volatile("ldmatrix.sync.aligned.m8n8.x4.trans.shared.b16 {%0,%1,%2,%3},[%4];"
                 : "=r"(r[0]), "=r"(r[1]), "=r"(r[2]), "=r"(r[3]) : "r"(a));
}
__device__ __forceinline__ void mma_bf(float* c, const uint32_t* a, uint32_t b0, uint32_t b1) {
    asm volatile(
        "mma.sync.aligned.m16n8k16.row.col.f32.bf16.bf16.f32 "
        "{%0,%1,%2,%3},{%4,%5,%6,%7},{%8,%9},{%0,%1,%2,%3};"
        : "+f"(c[0]), "+f"(c[1]), "+f"(c[2]), "+f"(c[3])
        : "r"(a[0]), "r"(a[1]), "r"(a[2]), "r"(a[3]), "r"(b0), "r"(b1));
}
__device__ __forceinline__ void split2(float x, float y, uint32_t& hi, uint32_t& lo) {
    __nv_bfloat16 hx = __float2bfloat16_rn(x);
    __nv_bfloat16 hy = __float2bfloat16_rn(y);
    __nv_bfloat16 lx = __float2bfloat16_rn(x - __bfloat162float(hx));
    __nv_bfloat16 ly = __float2bfloat16_rn(y - __bfloat162float(hy));
    hi = (uint32_t)__bfloat16_as_ushort(hx) | ((uint32_t)__bfloat16_as_ushort(hy) << 16);
    lo = (uint32_t)__bfloat16_as_ushort(lx) | ((uint32_t)__bfloat16_as_ushort(ly) << 16);
}
__device__ __forceinline__ void cpa16(uint32_t dst, const void* src) {
    asm volatile("cp.async.ca.shared.global [%0],[%1],16;" :: "r"(dst), "l"(src));
}
__device__ __forceinline__ void cpa_commit() {
    asm volatile("cp.async.commit_group;" ::: "memory");
}
__device__ __forceinline__ void cpa_wait1() {
    asm volatile("cp.async.wait_group 1;" ::: "memory");
}
__device__ __forceinline__ void cpa_wait0() {
    asm volatile("cp.async.wait_group 0;" ::: "memory");
}

// ---------------------------------------------------------------------------
// Split-convert kernels
// ---------------------------------------------------------------------------
__global__ __launch_bounds__(256) void cvt_w(
    const float* __restrict__ w0, const float* __restrict__ w1,
    const float* __restrict__ w2, const float* __restrict__ w3,
    __nv_bfloat16* __restrict__ hi, __nv_bfloat16* __restrict__ lo)
{
    const float* src = (blockIdx.y == 0) ? w0 : (blockIdx.y == 1) ? w1 : (blockIdx.y == 2) ? w2 : w3;
    const size_t base = (size_t)blockIdx.y * DD;
    const size_t i = ((size_t)blockIdx.x * 256 + threadIdx.x) * 8;
    float4 f0 = *(const float4*)(src + i);
    float4 f1 = *(const float4*)(src + i + 4);
    uint4 h, l;
    split2(f0.x, f0.y, h.x, l.x);
    split2(f0.z, f0.w, h.y, l.y);
    split2(f1.x, f1.y, h.z, l.z);
    split2(f1.z, f1.w, h.w, l.w);
    *(uint4*)(hi + base + i) = h;
    *(uint4*)(lo + base + i) = l;
}

__global__ __launch_bounds__(256) void cvt_x(
    const float* __restrict__ src,
    __nv_bfloat16* __restrict__ hi, __nv_bfloat16* __restrict__ lo)
{
    const size_t i = ((size_t)blockIdx.x * 256 + threadIdx.x) * 8;
    float4 f0 = *(const float4*)(src + i);
    float4 f1 = *(const float4*)(src + i + 4);
    uint4 h, l;
    split2(f0.x, f0.y, h.x, l.x);
    split2(f0.z, f0.w, h.y, l.y);
    split2(f1.x, f1.y, h.z, l.z);
    split2(f1.z, f1.w, h.w, l.w);
    *(uint4*)(hi + i) = h;
    *(uint4*)(lo + i) = l;
}

// ---------------------------------------------------------------------------
// mma.sync split-bf16 GEMM (at HMMA architectural floor)
// ---------------------------------------------------------------------------
__global__ __launch_bounds__(256, 2) void gemm_mma(
    const __nv_bfloat16* __restrict__ Ahi, const __nv_bfloat16* __restrict__ Alo,
    const __nv_bfloat16* __restrict__ Whi, const __nv_bfloat16* __restrict__ Wlo,
    int wzoff,
    float* __restrict__ C0, float* __restrict__ C1, float* __restrict__ C2)
{
    float* C = (blockIdx.z == 0) ? C0 : (blockIdx.z == 1) ? C1 : C2;
    const size_t woff = (size_t)(blockIdx.z + wzoff) * DD;

    extern __shared__ char smem[];
    const uint32_t sb = smem_u32(smem);
    const int tid  = threadIdx.x;
    const int wid  = tid >> 5;
    const int lane = tid & 31;
    const int wm   = wid & 1;
    const int wn   = wid >> 1;

    const int m0 = blockIdx.y * 128;
    const int n0 = blockIdx.x * 128;

    const __nv_bfloat16* AhiB = Ahi + (size_t)m0 * D_;
    const __nv_bfloat16* AloB = Alo + (size_t)m0 * D_;
    const __nv_bfloat16* WhiB = Whi + woff + n0;
    const __nv_bfloat16* WloB = Wlo + woff + n0;

    float acc[4][4][4];
#pragma unroll
    for (int mt = 0; mt < 4; ++mt)
#pragma unroll
        for (int nt = 0; nt < 4; ++nt)
#pragma unroll
            for (int e = 0; e < 4; ++e) acc[mt][nt][e] = 0.0f;

    const int a_r   = (lane & 7) + ((lane >> 3) & 1) * 8;
    const int a_kb  = (lane >> 4) * 16;
    const int b_kr  = (lane & 7) + (lane >> 4) * 8;
    const int b_nb  = ((lane >> 3) & 1) * 16;

    auto issue_stage = [&](int ch, int s) {
        const uint32_t stA = sb + s * STAGE;
        const uint32_t stB = stA + 2 * A_TILE;
#pragma unroll
        for (int i = 0; i < 2; ++i) {
            const int c = tid * 2 + i;
            const int ar = c >> 2, akc = c & 3;
            const size_t aoff = (size_t)ar * D_ + ch * BK + akc * 8;
            const uint32_t adst = stA + ar * A_ROW_B + akc * 16;
            cpa16(adst, AhiB + aoff);
            cpa16(adst + A_TILE, AloB + aoff);
            const int br = c >> 4, bnc = c & 15;
            const size_t boff = (size_t)(ch * BK + br) * D_ + bnc * 8;
            const uint32_t bdst = stB + br * B_ROW_B + bnc * 16;
            cpa16(bdst, WhiB + boff);
            cpa16(bdst + B_TILE, WloB + boff);
        }
        cpa_commit();
    };

    issue_stage(0, 0);

    for (int ch = 0; ch < NCHUNK; ++ch) {
        const int s = ch & 1;
        if (ch + 1 < NCHUNK) { issue_stage(ch + 1, s ^ 1); cpa_wait1(); }
        else cpa_wait0();
        __syncthreads();

        const uint32_t Ah = sb + s * STAGE;
        const uint32_t Al = Ah + A_TILE;
        const uint32_t Bh = Ah + 2 * A_TILE;
        const uint32_t Bl = Bh + B_TILE;

#pragma unroll
        for (int kc = 0; kc < 2; ++kc) {
            uint32_t ah[4][4], al[4][4];
            uint32_t bh[4][2], bl[4][2];
            const uint32_t a_addr = (uint32_t)((wm * 64 + a_r) * A_ROW_B + kc * 32 + a_kb);
#pragma unroll
            for (int mt = 0; mt < 4; ++mt) {
                ldsm4(ah[mt], Ah + a_addr + mt * 16 * A_ROW_B);
                ldsm4(al[mt], Al + a_addr + mt * 16 * A_ROW_B);
            }
            const uint32_t b_addr = (uint32_t)((kc * 16 + b_kr) * B_ROW_B + (wn * 32) * 2 + b_nb);
#pragma unroll
            for (int p = 0; p < 2; ++p) {
                uint32_t rh[4], rl[4];
                ldsm4t(rh, Bh + b_addr + p * 32);
                ldsm4t(rl, Bl + b_addr + p * 32);
                bh[2 * p][0] = rh[0]; bh[2 * p][1] = rh[2];
                bh[2 * p + 1][0] = rh[1]; bh[2 * p + 1][1] = rh[3];
                bl[2 * p][0] = rl[0]; bl[2 * p][1] = rl[2];
                bl[2 * p + 1][0] = rl[1]; bl[2 * p + 1][1] = rl[3];
            }
#pragma unroll
            for (int mt = 0; mt < 4; ++mt)
#pragma unroll
                for (int nt = 0; nt < 4; ++nt)
                    mma_bf(acc[mt][nt], ah[mt], bh[nt][0], bh[nt][1]);
#pragma unroll
            for (int mt = 0; mt < 4; ++mt)
#pragma unroll
                for (int nt = 0; nt < 4; ++nt)
                    mma_bf(acc[mt][nt], ah[mt], bl[nt][0], bl[nt][1]);
#pragma unroll
            for (int mt = 0; mt < 4; ++mt)
#pragma unroll
                for (int nt = 0; nt < 4; ++nt)
                    mma_bf(acc[mt][nt], al[mt], bh[nt][0], bh[nt][1]);
        }
        __syncthreads();
    }

    const int gr = lane >> 2;
    const int gc = lane & 3;
#pragma unroll
    for (int mt = 0; mt < 4; ++mt) {
        const int row = m0 + wm * 64 + mt * 16 + gr;
        float* c0 = C + (size_t)row * D_ + n0 + wn * 32;
        float* c1 = C + (size_t)(row + 8) * D_ + n0 + wn * 32;
#pragma unroll
        for (int nt = 0; nt < 4; ++nt) {
            *(float2*)(c0 + nt * 8 + gc * 2) = make_float2(acc[mt][nt][0], acc[mt][nt][1]);
            *(float2*)(c1 + nt * 8 + gc * 2) = make_float2(acc[mt][nt][2], acc[mt][nt][3]);
        }
    }
}

// ---------------------------------------------------------------------------
__global__ __launch_bounds__(256) void rmsnorm_k(float* __restrict__ X,
                                                 const float* __restrict__ w) {
    const int row  = (blockIdx.x * 256 + threadIdx.x) >> 5;
    const int lane = threadIdx.x & 31;
    float* p = X + (size_t)row * 128 + lane * 4;
    float4 v = *(float4*)p;
    float ss = v.x * v.x + v.y * v.y + v.z * v.z + v.w * v.w;
#pragma unroll
    for (int o = 16; o; o >>= 1) ss += __shfl_xor_sync(0xffffffffu, ss, o);
    float r = rsqrtf(ss * (1.0f / 128.0f) + 1e-6f);
    float4 wv = *(const float4*)(w + lane * 4);
    v.x *= r * wv.x; v.y *= r * wv.y; v.z *= r * wv.z; v.w *= r * wv.w;
    *(float4*)p = v;
}

// rmsnorm + split in one pass (for K)
__global__ __launch_bounds__(256) void rmsnorm_split(const float* __restrict__ X,
                                                     const float* __restrict__ w,
                                                     __nv_bfloat16* __restrict__ hi,
                                                     __nv_bfloat16* __restrict__ lo) {
    const int row  = (blockIdx.x * 256 + threadIdx.x) >> 5;
    const int lane = threadIdx.x & 31;
    const float* p = X + (size_t)row * 128 + lane * 4;
    float4 v = *(const float4*)p;
    float ss = v.x * v.x + v.y * v.y + v.z * v.z + v.w * v.w;
#pragma unroll
    for (int o = 16; o; o >>= 1) ss += __shfl_xor_sync(0xffffffffu, ss, o);
    float r = rsqrtf(ss * (1.0f / 128.0f) + 1e-6f);
    float4 wv = *(const float4*)(w + lane * 4);
    v.x *= r * wv.x; v.y *= r * wv.y; v.z *= r * wv.z; v.w *= r * wv.w;
    uint32_t h0, l0, h1, l1;
    split2(v.x, v.y, h0, l0);
    split2(v.z, v.w, h1, l1);
    *(uint2*)(hi + (size_t)row * 128 + lane * 4) = make_uint2(h0, h1);
    *(uint2*)(lo + (size_t)row * 128 + lane * 4) = make_uint2(l0, l1);
}

// ---------------------------------------------------------------------------
// MMA flash attention. CTA = 64 queries (one head). 8 warps = 4 q-groups(mg)
// x 2 key-splits(sp). 32-key tiles double-buffered (Khi,Klo,Vhi,Vlo).
// Split-bf16 (3 MMAs) QK and PV.
// ---------------------------------------------------------------------------
__global__ __launch_bounds__(256, 2) void attn_mma(
    const float* __restrict__ Qf,
    const __nv_bfloat16* __restrict__ CKhi, const __nv_bfloat16* __restrict__ CKlo,
    const __nv_bfloat16* __restrict__ CVhi, const __nv_bfloat16* __restrict__ CVlo,
    const __nv_bfloat16* __restrict__ NKhi, const __nv_bfloat16* __restrict__ NKlo,
    const __nv_bfloat16* __restrict__ NVhi, const __nv_bfloat16* __restrict__ NVlo,
    float* __restrict__ O)
{
    extern __shared__ char asmem[];
    const uint32_t sb = smem_u32(asmem);

    const int tid  = threadIdx.x;
    const int wid  = tid >> 5;
    const int lane = tid & 31;
    const int mg   = wid >> 1;
    const int sp   = wid & 1;
    const int h    = blockIdx.y;
    const int b    = blockIdx.z;
    const int q0   = blockIdx.x * 64;

    const float scale = 0.08838834764831845f;

    const uint32_t Qhi_o = sb;
    const uint32_t Qlo_o = sb + AQ_COMP;
    const uint32_t STG0  = sb + 2 * AQ_COMP;

    // ---- fill Q (64 rows, pre-scaled, split) ----
    {
        const int row = tid >> 2;
        const int d0  = (tid & 3) * 32;
        const float* qp = Qf + ((size_t)(b * L_ + q0 + row) * H_ + h) * Dh_ + d0;
        const uint32_t dst = (uint32_t)(row * ARB + d0 * 2);
#pragma unroll
        for (int i = 0; i < 16; ++i) {
            float2 f = *(const float2*)(qp + 2 * i);
            uint32_t hreg, lreg;
            split2(f.x * scale, f.y * scale, hreg, lreg);
            *(uint32_t*)(asmem + dst + 4 * i) = hreg;
            *(uint32_t*)(asmem + AQ_COMP + dst + 4 * i) = lreg;
        }
    }
    __syncthreads();

    const int a_r  = (lane & 7) + ((lane >> 3) & 1) * 8;
    const int a_kb = (lane >> 4) * 16;
    const int b_kr = (lane & 7) + (lane >> 4) * 8;
    const int b_nb = ((lane >> 3) & 1) * 16;

    float o[16][4];
#pragma unroll
    for (int nt = 0; nt < 16; ++nt)
#pragma unroll
        for (int e = 0; e < 4; ++e) o[nt][e] = 0.0f;
    float m0 = -1e30f, m1 = -1e30f, l0 = 0.0f, l1 = 0.0f;

    const int wlim = WINS_ + q0 + mg * 16;
    const int lim0 = wlim + (lane >> 2);
    const int lim1 = lim0 + 8;
    const int n_t  = (WINS_ + q0 + 64) / 32;

    auto issue_tile = [&](int t, int s) {
        const int sg = t * 32 + (tid >> 3);
        const __nv_bfloat16 *kh, *kl, *vh, *vl;
        if (sg < WINS_) {
            const int src = (sg < SINK_) ? sg : sg + L_;
            const size_t off = (((size_t)b * S_ + src) * H_ + h) * Dh_;
            kh = CKhi + off; kl = CKlo + off; vh = CVhi + off; vl = CVlo + off;
        } else {
            const size_t off = (((size_t)b * L_ + (sg - WINS_)) * H_ + h) * Dh_;
            kh = NKhi + off; kl = NKlo + off; vh = NVhi + off; vl = NVlo + off;
        }
        const uint32_t base = STG0 + s * AT_STG + (tid >> 3) * ARB;
#pragma unroll
        for (int i = 0; i < 2; ++i) {
            const int c16 = (tid & 7) * 2 + i;
            const uint32_t d = base + c16 * 16;
            cpa16(d, kh + c16 * 8);
            cpa16(d + AT_COMP, kl + c16 * 8);
            cpa16(d + 2 * AT_COMP, vh + c16 * 8);
            cpa16(d + 3 * AT_COMP, vl + c16 * 8);
        }
        cpa_commit();
    };

    issue_tile(0, 0);

    for (int t = 0; t < n_t; ++t) {
        const int s = t & 1;
        cpa_wait0();
        __syncthreads();
        if (t + 1 < n_t) issue_tile(t + 1, s ^ 1);

        const int colbase = t * 32 + sp * 16;
        if (colbase <= wlim + 15) {
            const uint32_t Khi_s = STG0 + s * AT_STG;
            const uint32_t Klo_s = Khi_s + AT_COMP;
            const uint32_t Vhi_s = Khi_s + 2 * AT_COMP;
            const uint32_t Vlo_s = Khi_s + 3 * AT_COMP;

            // ---- QK^T ----
            float sf[2][4];
#pragma unroll
            for (int nt = 0; nt < 2; ++nt)
#pragma unroll
                for (int e = 0; e < 4; ++e) sf[nt][e] = 0.0f;

#pragma unroll
            for (int ks = 0; ks < 8; ++ks) {
                const uint32_t qa = (uint32_t)((mg * 16 + a_r) * ARB + ks * 32 + a_kb);
                const uint32_t ka = (uint32_t)((sp * 16 + a_r) * ARB + ks * 32 + a_kb);
                uint32_t qh4[4], ql4[4], kh4[4], kl4[4];
                ldsm4(qh4, Qhi_o + qa);
                ldsm4(ql4, Qlo_o + qa);
                ldsm4(kh4, Khi_s + ka);
                ldsm4(kl4, Klo_s + ka);
                mma_bf(sf[0], qh4, kh4[0], kh4[2]);
                mma_bf(sf[1], qh4, kh4[1], kh4[3]);
                mma_bf(sf[0], qh4, kl4[0], kl4[2]);
                mma_bf(sf[1], qh4, kl4[1], kl4[3]);
                mma_bf(sf[0], ql4, kh4[0], kh4[2]);
                mma_bf(sf[1], ql4, kh4[1], kh4[3]);
            }

            // ---- mask ----
            if (colbase + 15 > wlim) {
                const int c0m = colbase + (lane & 3) * 2;
#pragma unroll
                for (int nt = 0; nt < 2; ++nt) {
                    const int cA = c0m + nt * 8, cB = cA + 1;
                    if (cA > lim0) sf[nt][0] = -1e30f;
                    if (cB > lim0) sf[nt][1] = -1e30f;
                    if (cA > lim1) sf[nt][2] = -1e30f;
                    if (cB > lim1) sf[nt][3] = -1e30f;
                }
            }

            // ---- online softmax ----
            float rm0 = fmaxf(fmaxf(sf[0][0], sf[0][1]), fmaxf(sf[1][0], sf[1][1]));
            float rm1 = fmaxf(fmaxf(sf[0][2], sf[0][3]), fmaxf(sf[1][2], sf[1][3]));
            rm0 = fmaxf(rm0, __shfl_xor_sync(0xffffffffu, rm0, 1));
            rm0 = fmaxf(rm0, __shfl_xor_sync(0xffffffffu, rm0, 2));
            rm1 = fmaxf(rm1, __shfl_xor_sync(0xffffffffu, rm1, 1));
            rm1 = fmaxf(rm1, __shfl_xor_sync(0xffffffffu, rm1, 2));
            const float mt0 = fmaxf(m0, rm0), mt1 = fmaxf(m1, rm1);
            const float al0 = __expf(m0 - mt0), al1 = __expf(m1 - mt1);
            m0 = mt0; m1 = mt1;

            float p[2][4];
#pragma unroll
            for (int nt = 0; nt < 2; ++nt) {
                p[nt][0] = __expf(sf[nt][0] - mt0);
                p[nt][1] = __expf(sf[nt][1] - mt0);
                p[nt][2] = __expf(sf[nt][2] - mt1);
                p[nt][3] = __expf(sf[nt][3] - mt1);
            }
            float rs0 = p[0][0] + p[0][1] + p[1][0] + p[1][1];
            float rs1 = p[0][2] + p[0][3] + p[1][2] + p[1][3];
            rs0 += __shfl_xor_sync(0xffffffffu, rs0, 1);
            rs0 += __shfl_xor_sync(0xffffffffu, rs0, 2);
            rs1 += __shfl_xor_sync(0xffffffffu, rs1, 1);
            rs1 += __shfl_xor_sync(0xffffffffu, rs1, 2);
            l0 = l0 * al0 + rs0;
            l1 = l1 * al1 + rs1;

            if (__any_sync(0xffffffffu, (al0 < 1.0f) | (al1 < 1.0f))) {
#pragma unroll
                for (int nt = 0; nt < 16; ++nt) {
                    o[nt][0] *= al0; o[nt][1] *= al0;
                    o[nt][2] *= al1; o[nt][3] *= al1;
                }
            }

            // ---- P fragments ----
            uint32_t pah[4], pal[4];
            split2(p[0][0], p[0][1], pah[0], pal[0]);
            split2(p[0][2], p[0][3], pah[1], pal[1]);
            split2(p[1][0], p[1][1], pah[2], pal[2]);
            split2(p[1][2], p[1][3], pah[3], pal[3]);

            // ---- PV (split V: Ph*Vh + Ph*Vl + Pl*Vh) ----
#pragma unroll
            for (int g = 0; g < 8; ++g) {
                const uint32_t va = (uint32_t)((sp * 16 + b_kr) * ARB + g * 32 + b_nb);
                uint32_t vh4[4], vl4[4];
                ldsm4t(vh4, Vhi_s + va);
                ldsm4t(vl4, Vlo_s + va);
                mma_bf(o[2 * g],     pah, vh4[0], vh4[2]);
                mma_bf(o[2 * g + 1], pah, vh4[1], vh4[3]);
                mma_bf(o[2 * g],     pah, vl4[0], vl4[2]);
                mma_bf(o[2 * g + 1], pah, vl4[1], vl4[3]);
                mma_bf(o[2 * g],     pal, vh4[0], vh4[2]);
                mma_bf(o[2 * g + 1], pal, vh4[1], vh4[3]);
            }
        }
    }

    // ---- merge across the 2 sp warps of each mg group ----
    __syncthreads();
    {
        const int r0 = lane >> 2, c0 = (lane & 3) * 2;
#pragma unroll
        for (int nt = 0; nt < 16; ++nt) {
            *(float2*)(asmem + wid * 8192 + r0 * 512 + (nt * 8 + c0) * 4) =
                make_float2(o[nt][0], o[nt][1]);
            *(float2*)(asmem + wid * 8192 + (r0 + 8) * 512 + (nt * 8 + c0) * 4) =
                make_float2(o[nt][2], o[nt][3]);
        }
        if ((lane & 3) == 0) {
            *(float2*)(asmem + 65536 + (wid * 16 + r0) * 8)     = make_float2(m0, l0);
            *(float2*)(asmem + 65536 + (wid * 16 + r0 + 8) * 8) = make_float2(m1, l1);
        }
    }
    __syncthreads();

    {
        const int row = tid >> 2;
        const int d0  = (tid & 3) * 32;
        const int mg2 = row >> 4, rr = row & 15;
        float2 ml0 = *(const float2*)(asmem + 65536 + ((2 * mg2) * 16 + rr) * 8);
        float2 ml1 = *(const float2*)(asmem + 65536 + ((2 * mg2 + 1) * 16 + rr) * 8);
        const float M = fmaxf(ml0.x, ml1.x);
        const float w0 = __expf(ml0.x - M), w1 = __expf(ml1.x - M);
        const float inv = 1.0f / (w0 * ml0.y + w1 * ml1.y);
        const float* b0 = (const float*)(asmem + (2 * mg2) * 8192 + rr * 512 + d0 * 4);
        const float* b1 = (const float*)(asmem + (2 * mg2 + 1) * 8192 + rr * 512 + d0 * 4);
        float* dst = O + (size_t)(b * L_ + q0 + row) * D_ + h * 128 + d0;
#pragma unroll
        for (int j = 0; j < 8; ++j) {
            float4 f0 = *(const float4*)(b0 + 4 * j);
            float4 f1 = *(const float4*)(b1 + 4 * j);
            *(float4*)(dst + 4 * j) = make_float4(
                (w0 * f0.x + w1 * f1.x) * inv, (w0 * f0.y + w1 * f1.y) * inv,
                (w0 * f0.z + w1 * f1.z) * inv, (w0 * f0.w + w1 * f1.w) * inv);
        }
    }
}

// ---------------------------------------------------------------------------
extern "C" void kernel_launch(void* const* d_in, const int* in_sizes, int n_in,
                              void* d_out, int out_size) {
    const float* x  = (const float*)d_in[0];
    const float* ck = (const float*)d_in[1];
    const float* cv = (const float*)d_in[2];
    const float* Wq = (const float*)d_in[3];
    const float* Wk = (const float*)d_in[4];
    const float* Wv = (const float*)d_in[5];
    const float* Wo = (const float*)d_in[6];
    const float* qw = (const float*)d_in[7];
    const float* kw = (const float*)d_in[8];
    float* out = (float*)d_out;

    void *pq, *pk, *pv, *po, *pwh, *pwl, *pxh, *pxl, *poh, *pol;
    void *pckh, *pckl, *pcvh, *pcvl, *pnkh, *pnkl, *pnvh, *pnvl;
    cudaGetSymbolAddress(&pq, g_q);
    cudaGetSymbolAddress(&pk, g_k);
    cudaGetSymbolAddress(&pv, g_v);
    cudaGetSymbolAddress(&po, g_o);
    cudaGetSymbolAddress(&pwh, g_whi);
    cudaGetSymbolAddress(&pwl, g_wlo);
    cudaGetSymbolAddress(&pxh, g_xhi);
    cudaGetSymbolAddress(&pxl, g_xlo);
    cudaGetSymbolAddress(&poh, g_ohi);
    cudaGetSymbolAddress(&pol, g_olo);
    cudaGetSymbolAddress(&pckh, g_ckhi);
    cudaGetSymbolAddress(&pckl, g_cklo);
    cudaGetSymbolAddress(&pcvh, g_cvhi);
    cudaGetSymbolAddress(&pcvl, g_cvlo);
    cudaGetSymbolAddress(&pnkh, g_nkhi);
    cudaGetSymbolAddress(&pnkl, g_nklo);
    cudaGetSymbolAddress(&pnvh, g_nvhi);
    cudaGetSymbolAddress(&pnvl, g_nvlo);

    float* Qb = (float*)pq;
    float* Kb = (float*)pk;
    float* Vb = (float*)pv;
    float* Ob = (float*)po;
    __nv_bfloat16* Whi = (__nv_bfloat16*)pwh;
    __nv_bfloat16* Wlo = (__nv_bfloat16*)pwl;
    __nv_bfloat16* Xhi = (__nv_bfloat16*)pxh;
    __nv_bfloat16* Xlo = (__nv_bfloat16*)pxl;
    __nv_bfloat16* Ohi = (__nv_bfloat16*)poh;
    __nv_bfloat16* Olo = (__nv_bfloat16*)pol;

    cudaFuncSetAttribute(gemm_mma, cudaFuncAttributeMaxDynamicSharedMemorySize, SMEMT);
    cudaFuncSetAttribute(attn_mma, cudaFuncAttributeMaxDynamicSharedMemorySize, ATT_SMEM);

    const int cache_blocks = (int)(CACHE_E / 2048);

    // Side stream: cache conversions overlap the (compute-bound) QKV GEMM.
    cudaStream_t s2;
    cudaStreamCreateWithFlags(&s2, cudaStreamNonBlocking);
    cudaEvent_t e1, e2;
    cudaEventCreateWithFlags(&e1, cudaEventDisableTiming);
    cudaEventCreateWithFlags(&e2, cudaEventDisableTiming);

    cudaEventRecord(e1, 0);
    cudaStreamWaitEvent(s2, e1, 0);
    cvt_x<<<cache_blocks, 256, 0, s2>>>(ck, (__nv_bfloat16*)pckh, (__nv_bfloat16*)pckl);
    cvt_x<<<cache_blocks, 256, 0, s2>>>(cv, (__nv_bfloat16*)pcvh, (__nv_bfloat16*)pcvl);
    cudaEventRecord(e2, s2);

    // Main stream
    cvt_w<<<dim3(DD / 2048, 4), 256>>>(Wq, Wk, Wv, Wo, Whi, Wlo);
    cvt_x<<<(M_ * D_) / 2048, 256>>>(x, Xhi, Xlo);
    gemm_mma<<<dim3(D_ / 128, M_ / 128, 3), 256, SMEMT>>>(Xhi, Xlo, Whi, Wlo, 0, Qb, Kb, Vb);
    rmsnorm_k<<<(M_ * H_) / 8, 256>>>(Qb, qw);
    rmsnorm_split<<<(M_ * H_) / 8, 256>>>(Kb, kw, (__nv_bfloat16*)pnkh, (__nv_bfloat16*)pnkl);
    cvt_x<<<(M_ * D_) / 2048, 256>>>(Vb, (__nv_bfloat16*)pnvh, (__nv_bfloat16*)pnvl);

    // Join: attention needs the converted caches.
    cudaStreamWaitEvent(0, e2, 0);

    attn_mma<<<dim3(L_ / 64, H_, B_), 256, ATT_SMEM>>>(
        Qb,
        (const __nv_bfloat16*)pckh, (const __nv_bfloat16*)pckl,
        (const __nv_bfloat16*)pcvh, (const __nv_bfloat16*)pcvl,
        (const __nv_bfloat16*)pnkh, (const __nv_bfloat16*)pnkl,
        (const __nv_bfloat16*)pnvh, (const __nv_bfloat16*)pnvl,
        Ob);
    cvt_x<<<(M_ * D_) / 2048, 256>>>(Ob, Ohi, Olo);
    gemm_mma<<<dim3(D_ / 128, M_ / 128, 1), 256, SMEMT>>>(Ohi, Olo, Whi, Wlo, 3, out, out, out);
}